// round 11
// baseline (speedup 1.0000x reference)
#include <cuda_runtime.h>
#include <cuda_fp16.h>
#include <cstdint>

// Problem shapes (fixed per reference)
#define B_  4
#define T_  64
#define L_  128
#define D_  768
#define H_  12
#define HD_ 64   // head dim

// -------------------- scratch (device globals; no allocation) --------------------
__device__ float  g_kvproj[B_ * T_ * 2 * D_];            // fp32 k|v rows=(b,t)
__device__ __half g_tokh[(size_t)B_ * T_ * L_ * D_];     // fp16 token embeddings
__device__ __half g_Wqh[D_ * D_];                        // fp16 Wq

__device__ __forceinline__ uint32_t pack_h2(float lo, float hi) {
    __half2 h = __floats2half2_rn(lo, hi);
    return *reinterpret_cast<uint32_t*>(&h);
}

// -------------------- prep kernel: kvproj (blocks 0..191) + fp16 convert (rest) --------------------
// kvproj: C[256,1536] = edu @ concat(Wk,Wv)^T, BM=32 BN=64 BK=32.
// tofp16: tok (25.2M) then Wq (0.59M), 2048 fp32 per block.
#define KV_BLOCKS 192

__global__ __launch_bounds__(256)
void prep_kernel(const float* __restrict__ edu, const float* __restrict__ Wk,
                 const float* __restrict__ Wv, float* __restrict__ C,
                 const float* __restrict__ tok, const float* __restrict__ Wq) {
    const int tid = threadIdx.x;

    if (blockIdx.x >= KV_BLOCKS) {
        // ---- fp32 -> fp16 streaming convert ----
        const size_t NT = (size_t)B_ * T_ * L_ * D_;
        size_t i = ((size_t)(blockIdx.x - KV_BLOCKS) * 256 + tid) * 8;
        if (i < NT) {
            float4 a = *reinterpret_cast<const float4*>(tok + i);
            float4 b = *reinterpret_cast<const float4*>(tok + i + 4);
            uint4 o;
            o.x = pack_h2(a.x, a.y); o.y = pack_h2(a.z, a.w);
            o.z = pack_h2(b.x, b.y); o.w = pack_h2(b.z, b.w);
            *reinterpret_cast<uint4*>(g_tokh + i) = o;
        } else {
            size_t j = i - NT;
            if (j < (size_t)D_ * D_) {
                float4 a = *reinterpret_cast<const float4*>(Wq + j);
                float4 b = *reinterpret_cast<const float4*>(Wq + j + 4);
                uint4 o;
                o.x = pack_h2(a.x, a.y); o.y = pack_h2(a.z, a.w);
                o.z = pack_h2(b.x, b.y); o.w = pack_h2(b.z, b.w);
                *reinterpret_cast<uint4*>(g_Wqh + j) = o;
            }
        }
        return;
    }

    // ---- kv projection ----
    __shared__ float As[32][33];
    __shared__ float Bs[32][68];

    const int K = D_, N = 2 * D_;
    const int tx  = tid & 15;
    const int ty  = tid >> 4;
    const int row0 = (blockIdx.x / 24) * 32;
    const int col0 = (blockIdx.x % 24) * 64;

    const float* Bbase = (col0 < D_) ? Wk : Wv;
    const int    bn0   = (col0 < D_) ? col0 : (col0 - D_);

    float acc[2][4];
#pragma unroll
    for (int i = 0; i < 2; i++)
#pragma unroll
        for (int j = 0; j < 4; j++) acc[i][j] = 0.0f;

    for (int k0 = 0; k0 < K; k0 += 32) {
        {
            int r = tid >> 3, kq = tid & 7;
            float4 v = *reinterpret_cast<const float4*>(&edu[(size_t)(row0 + r) * K + k0 + kq * 4]);
            As[kq * 4 + 0][r] = v.x; As[kq * 4 + 1][r] = v.y;
            As[kq * 4 + 2][r] = v.z; As[kq * 4 + 3][r] = v.w;
        }
#pragma unroll
        for (int i = 0; i < 2; i++) {
            int idx = tid + i * 256;
            int r = idx >> 3, kq = idx & 7;
            float4 v = *reinterpret_cast<const float4*>(&Bbase[(size_t)(bn0 + r) * K + k0 + kq * 4]);
            Bs[kq * 4 + 0][r] = v.x; Bs[kq * 4 + 1][r] = v.y;
            Bs[kq * 4 + 2][r] = v.z; Bs[kq * 4 + 3][r] = v.w;
        }
        __syncthreads();

#pragma unroll
        for (int kk = 0; kk < 32; kk++) {
            float ar[2];
            ar[0] = As[kk][ty * 2 + 0];
            ar[1] = As[kk][ty * 2 + 1];
            float4 b4 = *reinterpret_cast<const float4*>(&Bs[kk][tx * 4]);
            acc[0][0] += ar[0] * b4.x; acc[0][1] += ar[0] * b4.y;
            acc[0][2] += ar[0] * b4.z; acc[0][3] += ar[0] * b4.w;
            acc[1][0] += ar[1] * b4.x; acc[1][1] += ar[1] * b4.y;
            acc[1][2] += ar[1] * b4.z; acc[1][3] += ar[1] * b4.w;
        }
        __syncthreads();
    }

#pragma unroll
    for (int i = 0; i < 2; i++) {
        float4 v = make_float4(acc[i][0], acc[i][1], acc[i][2], acc[i][3]);
        *reinterpret_cast<float4*>(&C[(size_t)(row0 + ty * 2 + i) * N + col0 + tx * 4]) = v;
    }
}

// -------------------- fused q-projection + M build + apply --------------------
// cp.async 3-stage pipeline, fp16 smem, 16B-granular swizzle, ldmatrix fragments.
// Swizzle: logical unit u (16B) of row r placed at u ^ swz(r), swz(r) = (r&3) ^ ((r>>2)&1).

#define QBM 128
#define QBN 64
#define STGB 12288                          // bytes per stage
#define STGW 3072                           // words per stage
#define ABYTES 8192                         // A region bytes
#define AWORDS 2048
#define KBW  (3 * STGW)                     // kb word offset
#define VBW  (KBW + T_ * HD_)
#define SPKW (VBW + T_ * HD_)
#define SMEM_WORDS (SPKW + T_)
#define SMEM_BYTES (SMEM_WORDS * 4)         // 69888 B

__device__ __forceinline__ int swz(int r) { return (r & 3) ^ ((r >> 2) & 1); }

__device__ __forceinline__ void cp16(uint32_t dst, const void* src) {
    asm volatile("cp.async.ca.shared.global [%0], [%1], 16;" :: "r"(dst), "l"(src));
}
#define CP_COMMIT() asm volatile("cp.async.commit_group;")
template <int N> __device__ __forceinline__ void cp_wait() {
    asm volatile("cp.async.wait_group %0;" :: "n"(N));
}

__device__ __forceinline__ void ldsm4(uint32_t& r0, uint32_t& r1, uint32_t& r2, uint32_t& r3,
                                      uint32_t addr) {
    asm volatile("ldmatrix.sync.aligned.m8n8.x4.shared.b16 {%0,%1,%2,%3}, [%4];"
                 : "=r"(r0), "=r"(r1), "=r"(r2), "=r"(r3) : "r"(addr));
}

__device__ __forceinline__ void mma_f16(float c[4], uint32_t a0, uint32_t a1,
                                        uint32_t a2, uint32_t a3,
                                        uint32_t b0, uint32_t b1) {
    asm volatile(
        "mma.sync.aligned.m16n8k16.row.col.f32.f16.f16.f32 "
        "{%0,%1,%2,%3}, {%4,%5,%6,%7}, {%8,%9}, {%0,%1,%2,%3};"
        : "+f"(c[0]), "+f"(c[1]), "+f"(c[2]), "+f"(c[3])
        : "r"(a0), "r"(a1), "r"(a2), "r"(a3), "r"(b0), "r"(b1));
}

// phase-2 scalar word store into swizzled layout: word w (0..15) of row r
__device__ __forceinline__ void sw_store_w(uint32_t* region, int r, int w, uint32_t v) {
    region[r * 16 + ((((w >> 2) ^ swz(r)) << 2) | (w & 3))] = v;
}

// one BK=32 stage of mma via ldmatrix; offsets are byte offsets relative to stage base
__device__ __forceinline__ void mma_stage(uint32_t sbase, const uint32_t offA[2][2],
                                          const uint32_t offB[2][2], float acc[2][4][4]) {
#pragma unroll
    for (int ks = 0; ks < 2; ks++) {
        uint32_t a[2][4], bb[2][4];
#pragma unroll
        for (int mt = 0; mt < 2; mt++)
            ldsm4(a[mt][0], a[mt][1], a[mt][2], a[mt][3], sbase + offA[mt][ks]);
#pragma unroll
        for (int P = 0; P < 2; P++)
            ldsm4(bb[P][0], bb[P][1], bb[P][2], bb[P][3], sbase + offB[P][ks]);
#pragma unroll
        for (int mt = 0; mt < 2; mt++)
#pragma unroll
            for (int nt = 0; nt < 4; nt++) {
                const int P = nt >> 1, pp = nt & 1;
                mma_f16(acc[mt][nt], a[mt][0], a[mt][1], a[mt][2], a[mt][3],
                        bb[P][2 * pp], bb[P][2 * pp + 1]);
            }
    }
}

__global__ __launch_bounds__(256, 3)
void qgemm_fused_kernel(const float* __restrict__ tok, const int* __restrict__ spk,
                        float* __restrict__ out) {
    extern __shared__ uint32_t smem[];
    const uint32_t smem_s = (uint32_t)__cvta_generic_to_shared(smem);

    const int tid  = threadIdx.x;
    const int warp = tid >> 5;
    const int lane = tid & 31;
    const int gid  = lane >> 2;
    const int c4   = lane & 3;
    const int warp_m = warp & 3;
    const int warp_n = warp >> 2;

    const int hblk = blockIdx.x;
    const int bt   = blockIdx.y;
    const int b    = bt >> 6;
    const int tloc = bt & 63;
    const int row0 = bt * QBM;
    const int col0 = hblk * QBN;

    // ---- cp.async source/dest (relative byte offsets within stage) ----
    const int rA0 = tid >> 2,          uA0 = tid & 3;
    const int rA1 = (tid + 256) >> 2,  uA1 = tid & 3;   // idx+256: u unchanged, r += 64
    const int rB  = tid >> 2,          uB  = tid & 3;
    const __half* gA0 = g_tokh + (size_t)(row0 + rA0) * D_ + uA0 * 8;
    const __half* gA1 = g_tokh + (size_t)(row0 + rA1) * D_ + uA1 * 8;
    const __half* gB  = g_Wqh  + (size_t)(col0 + rB) * D_ + uB * 8;
    const uint32_t dA0 = rA0 * 64 + ((uA0 ^ swz(rA0)) << 4);
    const uint32_t dA1 = rA1 * 64 + ((uA1 ^ swz(rA1)) << 4);
    const uint32_t dB  = ABYTES + rB * 64 + ((uB ^ swz(rB)) << 4);

    // ---- ldmatrix lane offsets (relative byte offsets within stage) ----
    uint32_t offA[2][2], offB[2][2];
#pragma unroll
    for (int mt = 0; mt < 2; mt++)
#pragma unroll
        for (int ks = 0; ks < 2; ks++) {
            int r = warp_m * 32 + mt * 16 + (lane & 7) + ((lane >> 3) & 1) * 8;
            int u = 2 * ks + (lane >> 4);
            offA[mt][ks] = r * 64 + ((u ^ swz(r)) << 4);
        }
#pragma unroll
    for (int P = 0; P < 2; P++)
#pragma unroll
        for (int ks = 0; ks < 2; ks++) {
            int n = warp_n * 32 + P * 16 + (lane & 7) + ((lane >> 4) & 1) * 8;
            int u = 2 * ks + ((lane >> 3) & 1);
            offB[P][ks] = ABYTES + n * 64 + ((u ^ swz(n)) << 4);
        }

    float cacc[2][4][4];
#pragma unroll
    for (int mt = 0; mt < 2; mt++)
#pragma unroll
        for (int nt = 0; nt < 4; nt++)
#pragma unroll
            for (int i = 0; i < 4; i++) cacc[mt][nt][i] = 0.0f;

    // ---- prologue: stages 0,1 in flight ----
    {
        cp16(smem_s + 0 * STGB + dA0, gA0 + 0);
        cp16(smem_s + 0 * STGB + dA1, gA1 + 0);
        cp16(smem_s + 0 * STGB + dB,  gB  + 0);
        CP_COMMIT();
        cp16(smem_s + 1 * STGB + dA0, gA0 + 32);
        cp16(smem_s + 1 * STGB + dA1, gA1 + 32);
        cp16(smem_s + 1 * STGB + dB,  gB  + 32);
        CP_COMMIT();
    }

    // ---- main loop: 24 iterations, 3-stage pipeline, 1 barrier/iter ----
#pragma unroll
    for (int it = 0; it < 24; it++) {
        if (it == 23) cp_wait<0>(); else cp_wait<1>();
        __syncthreads();
        if (it + 2 < 24) {
            const uint32_t sb = smem_s + ((it + 2) % 3) * STGB;
            const int k = (it + 2) * 32;
            cp16(sb + dA0, gA0 + k);
            cp16(sb + dA1, gA1 + k);
            cp16(sb + dB,  gB  + k);
            CP_COMMIT();
        }
        mma_stage(smem_s + (it % 3) * STGB, offA, offB, cacc);
    }

    // ---------------- phase 2: build M in-block, then out = tok + q @ M ----------------
    float* kbs  = reinterpret_cast<float*>(smem + KBW);
    float* vbs  = reinterpret_cast<float*>(smem + VBW);
    int*   sspk = reinterpret_cast<int*>(smem + SPKW);

    // stage k,v for (b,h) into disjoint scratch (safe pre-sync)
    {
        const float* kvb = g_kvproj + (size_t)(b * T_) * (2 * D_);
#pragma unroll
        for (int i = 0; i < 4; i++) {
            int idx = tid + i * 256;
            int u = idx >> 4, dq = idx & 15;
            *reinterpret_cast<float4*>(&kbs[u * HD_ + dq * 4]) =
                *reinterpret_cast<const float4*>(&kvb[(size_t)u * (2 * D_) + hblk * HD_ + dq * 4]);
            *reinterpret_cast<float4*>(&vbs[u * HD_ + dq * 4]) =
                *reinterpret_cast<const float4*>(&kvb[(size_t)u * (2 * D_) + D_ + hblk * HD_ + dq * 4]);
        }
        if (tid < T_) sspk[tid] = spk[b * T_ + tid];
    }

    // write q (fp16) into A-areas of stages 0/1 (k-col c: stage = c>>5).
    // Safe without extra barrier: stages 0,1 were last read by mma(21),(22),
    // complete before barrier(23) for all threads; concurrent mma(23) reads stage 2 only.
    {
        uint32_t* Areg = smem + warp_n * STGW;
#pragma unroll
        for (int mt = 0; mt < 2; mt++) {
#pragma unroll
            for (int nt = 0; nt < 4; nt++) {
                int r = warp_m * 32 + mt * 16 + gid;
                int w = nt * 4 + c4;                 // word within 32-col stage
                sw_store_w(Areg, r,     w, pack_h2(cacc[mt][nt][0], cacc[mt][nt][1]));
                sw_store_w(Areg, r + 8, w, pack_h2(cacc[mt][nt][2], cacc[mt][nt][3]));
            }
        }
    }
    __syncthreads();   // kv/spk visible; q writes done

    // build M[d][e] (fp32, ascending u); store M^T (fp16) into B-areas of stages 0/1
    {
        const int dp = tid >> 3;            // d0 = 2dp, d1 = 2dp+1
        const int e0 = (tid & 7) * 8;
        const int d0 = dp * 2;
        const int myspk = sspk[tloc];
        float m0[8], m1[8];
#pragma unroll
        for (int j = 0; j < 8; j++) { m0[j] = 0.0f; m1[j] = 0.0f; }

        for (int u = 0; u <= tloc; u++) {
            if (sspk[u] != myspk) continue;
            float kd0 = kbs[u * HD_ + d0];
            float kd1 = kbs[u * HD_ + d0 + 1];
#pragma unroll
            for (int j4 = 0; j4 < 2; j4++) {
                float4 v4 = *reinterpret_cast<const float4*>(&vbs[u * HD_ + e0 + j4 * 4]);
                m0[j4 * 4 + 0] += kd0 * v4.x; m1[j4 * 4 + 0] += kd1 * v4.x;
                m0[j4 * 4 + 1] += kd0 * v4.y; m1[j4 * 4 + 1] += kd1 * v4.y;
                m0[j4 * 4 + 2] += kd0 * v4.z; m1[j4 * 4 + 2] += kd1 * v4.z;
                m0[j4 * 4 + 3] += kd0 * v4.w; m1[j4 * 4 + 3] += kd1 * v4.w;
            }
        }
        uint32_t* Breg = smem + (dp >> 4) * STGW + AWORDS;
#pragma unroll
        for (int j = 0; j < 8; j++) {
            sw_store_w(Breg, e0 + j, dp & 15, pack_h2(m0[j], m1[j]));
        }
    }
    __syncthreads();

    // apply: acc = q @ M over K=64 (stages 0,1)
#pragma unroll
    for (int mt = 0; mt < 2; mt++)
#pragma unroll
        for (int nt = 0; nt < 4; nt++)
#pragma unroll
            for (int i = 0; i < 4; i++) cacc[mt][nt][i] = 0.0f;

    mma_stage(smem_s + 0 * STGB, offA, offB, cacc);
    mma_stage(smem_s + 1 * STGB, offA, offB, cacc);

    // epilogue: out = tok + acc (exact fp32 residual)
#pragma unroll
    for (int mt = 0; mt < 2; mt++) {
#pragma unroll
        for (int nt = 0; nt < 4; nt++) {
            int row = row0 + warp_m * 32 + mt * 16 + gid;
            int col = col0 + warp_n * 32 + nt * 8 + c4 * 2;
            size_t a0 = (size_t)row * D_ + col;
            size_t a1 = (size_t)(row + 8) * D_ + col;
            float2 x0 = *reinterpret_cast<const float2*>(tok + a0);
            float2 x1 = *reinterpret_cast<const float2*>(tok + a1);
            *reinterpret_cast<float2*>(out + a0) =
                make_float2(cacc[mt][nt][0] + x0.x, cacc[mt][nt][1] + x0.y);
            *reinterpret_cast<float2*>(out + a1) =
                make_float2(cacc[mt][nt][2] + x1.x, cacc[mt][nt][3] + x1.y);
        }
    }
}

// -------------------- launch --------------------
extern "C" void kernel_launch(void* const* d_in, const int* in_sizes, int n_in,
                              void* d_out, int out_size) {
    const int*   spk = (const int*)d_in[1];
    const float* tok = (const float*)d_in[2];
    const float* edu = (const float*)d_in[3];
    const float* Wk  = (const float*)d_in[4];
    const float* Wv  = (const float*)d_in[5];
    const float* Wq  = (const float*)d_in[6];
    float* out = (float*)d_out;

    float* p_kvproj; cudaGetSymbolAddress((void**)&p_kvproj, g_kvproj);

    cudaFuncSetAttribute(qgemm_fused_kernel,
                         cudaFuncAttributeMaxDynamicSharedMemorySize, SMEM_BYTES);

    // 0) prep: kvproj (192 blocks) + fp16 convert of tok/Wq (12576 blocks), one launch
    {
        const size_t total = (size_t)B_ * T_ * L_ * D_ + (size_t)D_ * D_;
        int conv_blocks = (int)(total / (256 * 8));   // 12576, exact
        prep_kernel<<<KV_BLOCKS + conv_blocks, 256>>>(edu, Wk, Wv, p_kvproj, tok, Wq);
    }

    // 1) fused q projection + M build + apply + residual
    {
        dim3 grid(H_, B_ * T_);                       // (12, 256)
        qgemm_fused_kernel<<<grid, 256, SMEM_BYTES>>>(tok, spk, out);
    }
}

// round 12
// speedup vs baseline: 1.0072x; 1.0072x over previous
#include <cuda_runtime.h>
#include <cuda_fp16.h>
#include <cstdint>

// Problem shapes (fixed per reference)
#define B_  4
#define T_  64
#define L_  128
#define D_  768
#define H_  12
#define HD_ 64   // head dim

// -------------------- scratch (device globals; no allocation) --------------------
__device__ float  g_kvproj[B_ * T_ * 2 * D_];            // fp32 k|v rows=(b,t)
__device__ __half g_tokh[(size_t)B_ * T_ * L_ * D_];     // fp16 token embeddings
__device__ __half g_Wqh[D_ * D_];                        // fp16 Wq

__device__ __forceinline__ uint32_t pack_h2(float lo, float hi) {
    __half2 h = __floats2half2_rn(lo, hi);
    return *reinterpret_cast<uint32_t*>(&h);
}

// -------------------- prep kernel: kvproj (blocks 0..191) + fp16 convert (rest) --------------------
// kvproj: C[256,1536] = edu @ concat(Wk,Wv)^T, BM=32 BN=64 BK=32.
// tofp16: tok (25.2M) then Wq (0.59M), 2048 fp32 per block.
#define KV_BLOCKS 192

__global__ __launch_bounds__(256)
void prep_kernel(const float* __restrict__ edu, const float* __restrict__ Wk,
                 const float* __restrict__ Wv, float* __restrict__ C,
                 const float* __restrict__ tok, const float* __restrict__ Wq) {
    const int tid = threadIdx.x;

    if (blockIdx.x >= KV_BLOCKS) {
        // ---- fp32 -> fp16 streaming convert ----
        const size_t NT = (size_t)B_ * T_ * L_ * D_;
        size_t i = ((size_t)(blockIdx.x - KV_BLOCKS) * 256 + tid) * 8;
        if (i < NT) {
            float4 a = *reinterpret_cast<const float4*>(tok + i);
            float4 b = *reinterpret_cast<const float4*>(tok + i + 4);
            uint4 o;
            o.x = pack_h2(a.x, a.y); o.y = pack_h2(a.z, a.w);
            o.z = pack_h2(b.x, b.y); o.w = pack_h2(b.z, b.w);
            *reinterpret_cast<uint4*>(g_tokh + i) = o;
        } else {
            size_t j = i - NT;
            if (j < (size_t)D_ * D_) {
                float4 a = *reinterpret_cast<const float4*>(Wq + j);
                float4 b = *reinterpret_cast<const float4*>(Wq + j + 4);
                uint4 o;
                o.x = pack_h2(a.x, a.y); o.y = pack_h2(a.z, a.w);
                o.z = pack_h2(b.x, b.y); o.w = pack_h2(b.z, b.w);
                *reinterpret_cast<uint4*>(g_Wqh + j) = o;
            }
        }
        return;
    }

    // ---- kv projection ----
    __shared__ float As[32][33];
    __shared__ float Bs[32][68];

    const int K = D_, N = 2 * D_;
    const int tx  = tid & 15;
    const int ty  = tid >> 4;
    const int row0 = (blockIdx.x / 24) * 32;
    const int col0 = (blockIdx.x % 24) * 64;

    const float* Bbase = (col0 < D_) ? Wk : Wv;
    const int    bn0   = (col0 < D_) ? col0 : (col0 - D_);

    float acc[2][4];
#pragma unroll
    for (int i = 0; i < 2; i++)
#pragma unroll
        for (int j = 0; j < 4; j++) acc[i][j] = 0.0f;

    for (int k0 = 0; k0 < K; k0 += 32) {
        {
            int r = tid >> 3, kq = tid & 7;
            float4 v = *reinterpret_cast<const float4*>(&edu[(size_t)(row0 + r) * K + k0 + kq * 4]);
            As[kq * 4 + 0][r] = v.x; As[kq * 4 + 1][r] = v.y;
            As[kq * 4 + 2][r] = v.z; As[kq * 4 + 3][r] = v.w;
        }
#pragma unroll
        for (int i = 0; i < 2; i++) {
            int idx = tid + i * 256;
            int r = idx >> 3, kq = idx & 7;
            float4 v = *reinterpret_cast<const float4*>(&Bbase[(size_t)(bn0 + r) * K + k0 + kq * 4]);
            Bs[kq * 4 + 0][r] = v.x; Bs[kq * 4 + 1][r] = v.y;
            Bs[kq * 4 + 2][r] = v.z; Bs[kq * 4 + 3][r] = v.w;
        }
        __syncthreads();

#pragma unroll
        for (int kk = 0; kk < 32; kk++) {
            float ar[2];
            ar[0] = As[kk][ty * 2 + 0];
            ar[1] = As[kk][ty * 2 + 1];
            float4 b4 = *reinterpret_cast<const float4*>(&Bs[kk][tx * 4]);
            acc[0][0] += ar[0] * b4.x; acc[0][1] += ar[0] * b4.y;
            acc[0][2] += ar[0] * b4.z; acc[0][3] += ar[0] * b4.w;
            acc[1][0] += ar[1] * b4.x; acc[1][1] += ar[1] * b4.y;
            acc[1][2] += ar[1] * b4.z; acc[1][3] += ar[1] * b4.w;
        }
        __syncthreads();
    }

#pragma unroll
    for (int i = 0; i < 2; i++) {
        float4 v = make_float4(acc[i][0], acc[i][1], acc[i][2], acc[i][3]);
        *reinterpret_cast<float4*>(&C[(size_t)(row0 + ty * 2 + i) * N + col0 + tx * 4]) = v;
    }
}

// -------------------- fused q-projection + M build + apply --------------------
// cp.async 3-stage pipeline, fp16 smem, 16B-granular swizzle, ldmatrix fragments.
// Swizzle: logical unit u (16B) of row r placed at u ^ swz(r), swz(r) = (r&3) ^ ((r>>2)&1).

#define QBM 128
#define QBN 64
#define STGB 12288                          // bytes per stage
#define STGW 3072                           // words per stage
#define ABYTES 8192                         // A region bytes
#define AWORDS 2048
#define KBW  (3 * STGW)                     // kb word offset
#define VBW  (KBW + T_ * HD_)
#define SPKW (VBW + T_ * HD_)
#define SMEM_WORDS (SPKW + T_)
#define SMEM_BYTES (SMEM_WORDS * 4)         // 69888 B

__device__ __forceinline__ int swz(int r) { return (r & 3) ^ ((r >> 2) & 1); }

__device__ __forceinline__ void cp16(uint32_t dst, const void* src) {
    asm volatile("cp.async.ca.shared.global [%0], [%1], 16;" :: "r"(dst), "l"(src));
}
#define CP_COMMIT() asm volatile("cp.async.commit_group;")
template <int N> __device__ __forceinline__ void cp_wait() {
    asm volatile("cp.async.wait_group %0;" :: "n"(N));
}

__device__ __forceinline__ void ldsm4(uint32_t& r0, uint32_t& r1, uint32_t& r2, uint32_t& r3,
                                      uint32_t addr) {
    asm volatile("ldmatrix.sync.aligned.m8n8.x4.shared.b16 {%0,%1,%2,%3}, [%4];"
                 : "=r"(r0), "=r"(r1), "=r"(r2), "=r"(r3) : "r"(addr));
}

__device__ __forceinline__ void mma_f16(float c[4], uint32_t a0, uint32_t a1,
                                        uint32_t a2, uint32_t a3,
                                        uint32_t b0, uint32_t b1) {
    asm volatile(
        "mma.sync.aligned.m16n8k16.row.col.f32.f16.f16.f32 "
        "{%0,%1,%2,%3}, {%4,%5,%6,%7}, {%8,%9}, {%0,%1,%2,%3};"
        : "+f"(c[0]), "+f"(c[1]), "+f"(c[2]), "+f"(c[3])
        : "r"(a0), "r"(a1), "r"(a2), "r"(a3), "r"(b0), "r"(b1));
}

// phase-2 scalar word store into swizzled layout: word w (0..15) of row r
__device__ __forceinline__ void sw_store_w(uint32_t* region, int r, int w, uint32_t v) {
    region[r * 16 + ((((w >> 2) ^ swz(r)) << 2) | (w & 3))] = v;
}

// one BK=32 stage of mma via ldmatrix; offsets are byte offsets relative to stage base
__device__ __forceinline__ void mma_stage(uint32_t sbase, const uint32_t offA[2][2],
                                          const uint32_t offB[2][2], float acc[2][4][4]) {
#pragma unroll
    for (int ks = 0; ks < 2; ks++) {
        uint32_t a[2][4], bb[2][4];
#pragma unroll
        for (int mt = 0; mt < 2; mt++)
            ldsm4(a[mt][0], a[mt][1], a[mt][2], a[mt][3], sbase + offA[mt][ks]);
#pragma unroll
        for (int P = 0; P < 2; P++)
            ldsm4(bb[P][0], bb[P][1], bb[P][2], bb[P][3], sbase + offB[P][ks]);
#pragma unroll
        for (int mt = 0; mt < 2; mt++)
#pragma unroll
            for (int nt = 0; nt < 4; nt++) {
                const int P = nt >> 1, pp = nt & 1;
                mma_f16(acc[mt][nt], a[mt][0], a[mt][1], a[mt][2], a[mt][3],
                        bb[P][2 * pp], bb[P][2 * pp + 1]);
            }
    }
}

__global__ __launch_bounds__(256, 3)
void qgemm_fused_kernel(const float* __restrict__ tok, const int* __restrict__ spk,
                        float* __restrict__ out) {
    extern __shared__ uint32_t smem[];
    const uint32_t smem_s = (uint32_t)__cvta_generic_to_shared(smem);

    const int tid  = threadIdx.x;
    const int warp = tid >> 5;
    const int lane = tid & 31;
    const int gid  = lane >> 2;
    const int c4   = lane & 3;
    const int warp_m = warp & 3;
    const int warp_n = warp >> 2;

    const int hblk = blockIdx.x;
    const int bt   = blockIdx.y;
    const int b    = bt >> 6;
    const int tloc = bt & 63;
    const int row0 = bt * QBM;
    const int col0 = hblk * QBN;

    // ---- cp.async source/dest (relative byte offsets within stage) ----
    const int rA0 = tid >> 2,          uA0 = tid & 3;
    const int rA1 = (tid + 256) >> 2,  uA1 = tid & 3;   // idx+256: u unchanged, r += 64
    const int rB  = tid >> 2,          uB  = tid & 3;
    const __half* gA0 = g_tokh + (size_t)(row0 + rA0) * D_ + uA0 * 8;
    const __half* gA1 = g_tokh + (size_t)(row0 + rA1) * D_ + uA1 * 8;
    const __half* gB  = g_Wqh  + (size_t)(col0 + rB) * D_ + uB * 8;
    const uint32_t dA0 = rA0 * 64 + ((uA0 ^ swz(rA0)) << 4);
    const uint32_t dA1 = rA1 * 64 + ((uA1 ^ swz(rA1)) << 4);
    const uint32_t dB  = ABYTES + rB * 64 + ((uB ^ swz(rB)) << 4);

    // ---- ldmatrix lane offsets (relative byte offsets within stage) ----
    uint32_t offA[2][2], offB[2][2];
#pragma unroll
    for (int mt = 0; mt < 2; mt++)
#pragma unroll
        for (int ks = 0; ks < 2; ks++) {
            int r = warp_m * 32 + mt * 16 + (lane & 7) + ((lane >> 3) & 1) * 8;
            int u = 2 * ks + (lane >> 4);
            offA[mt][ks] = r * 64 + ((u ^ swz(r)) << 4);
        }
#pragma unroll
    for (int P = 0; P < 2; P++)
#pragma unroll
        for (int ks = 0; ks < 2; ks++) {
            int n = warp_n * 32 + P * 16 + (lane & 7) + ((lane >> 4) & 1) * 8;
            int u = 2 * ks + ((lane >> 3) & 1);
            offB[P][ks] = ABYTES + n * 64 + ((u ^ swz(n)) << 4);
        }

    float cacc[2][4][4];
#pragma unroll
    for (int mt = 0; mt < 2; mt++)
#pragma unroll
        for (int nt = 0; nt < 4; nt++)
#pragma unroll
            for (int i = 0; i < 4; i++) cacc[mt][nt][i] = 0.0f;

    // ---- prologue: stages 0,1 in flight ----
    {
        cp16(smem_s + 0 * STGB + dA0, gA0 + 0);
        cp16(smem_s + 0 * STGB + dA1, gA1 + 0);
        cp16(smem_s + 0 * STGB + dB,  gB  + 0);
        CP_COMMIT();
        cp16(smem_s + 1 * STGB + dA0, gA0 + 32);
        cp16(smem_s + 1 * STGB + dA1, gA1 + 32);
        cp16(smem_s + 1 * STGB + dB,  gB  + 32);
        CP_COMMIT();
    }

    // ---- main loop: 24 iterations, 3-stage pipeline, 1 barrier/iter ----
#pragma unroll
    for (int it = 0; it < 24; it++) {
        if (it == 23) cp_wait<0>(); else cp_wait<1>();
        __syncthreads();
        if (it + 2 < 24) {
            const uint32_t sb = smem_s + ((it + 2) % 3) * STGB;
            const int k = (it + 2) * 32;
            cp16(sb + dA0, gA0 + k);
            cp16(sb + dA1, gA1 + k);
            cp16(sb + dB,  gB  + k);
            CP_COMMIT();
        }
        mma_stage(smem_s + (it % 3) * STGB, offA, offB, cacc);
    }

    // ---------------- phase 2: build M in-block, then out = tok + q @ M ----------------
    float* kbs  = reinterpret_cast<float*>(smem + KBW);
    float* vbs  = reinterpret_cast<float*>(smem + VBW);
    int*   sspk = reinterpret_cast<int*>(smem + SPKW);

    // stage k,v for (b,h) into disjoint scratch (safe pre-sync)
    {
        const float* kvb = g_kvproj + (size_t)(b * T_) * (2 * D_);
#pragma unroll
        for (int i = 0; i < 4; i++) {
            int idx = tid + i * 256;
            int u = idx >> 4, dq = idx & 15;
            *reinterpret_cast<float4*>(&kbs[u * HD_ + dq * 4]) =
                *reinterpret_cast<const float4*>(&kvb[(size_t)u * (2 * D_) + hblk * HD_ + dq * 4]);
            *reinterpret_cast<float4*>(&vbs[u * HD_ + dq * 4]) =
                *reinterpret_cast<const float4*>(&kvb[(size_t)u * (2 * D_) + D_ + hblk * HD_ + dq * 4]);
        }
        if (tid < T_) sspk[tid] = spk[b * T_ + tid];
    }

    // write q (fp16) into A-areas of stages 0/1 (k-col c: stage = c>>5).
    // Safe without extra barrier: stages 0,1 were last read by mma(21),(22),
    // complete before barrier(23) for all threads; concurrent mma(23) reads stage 2 only.
    {
        uint32_t* Areg = smem + warp_n * STGW;
#pragma unroll
        for (int mt = 0; mt < 2; mt++) {
#pragma unroll
            for (int nt = 0; nt < 4; nt++) {
                int r = warp_m * 32 + mt * 16 + gid;
                int w = nt * 4 + c4;                 // word within 32-col stage
                sw_store_w(Areg, r,     w, pack_h2(cacc[mt][nt][0], cacc[mt][nt][1]));
                sw_store_w(Areg, r + 8, w, pack_h2(cacc[mt][nt][2], cacc[mt][nt][3]));
            }
        }
    }
    __syncthreads();   // kv/spk visible; q writes done

    // build M[d][e] (fp32, ascending u); store M^T (fp16) into B-areas of stages 0/1
    {
        const int dp = tid >> 3;            // d0 = 2dp, d1 = 2dp+1
        const int e0 = (tid & 7) * 8;
        const int d0 = dp * 2;
        const int myspk = sspk[tloc];
        float m0[8], m1[8];
#pragma unroll
        for (int j = 0; j < 8; j++) { m0[j] = 0.0f; m1[j] = 0.0f; }

        for (int u = 0; u <= tloc; u++) {
            if (sspk[u] != myspk) continue;
            float kd0 = kbs[u * HD_ + d0];
            float kd1 = kbs[u * HD_ + d0 + 1];
#pragma unroll
            for (int j4 = 0; j4 < 2; j4++) {
                float4 v4 = *reinterpret_cast<const float4*>(&vbs[u * HD_ + e0 + j4 * 4]);
                m0[j4 * 4 + 0] += kd0 * v4.x; m1[j4 * 4 + 0] += kd1 * v4.x;
                m0[j4 * 4 + 1] += kd0 * v4.y; m1[j4 * 4 + 1] += kd1 * v4.y;
                m0[j4 * 4 + 2] += kd0 * v4.z; m1[j4 * 4 + 2] += kd1 * v4.z;
                m0[j4 * 4 + 3] += kd0 * v4.w; m1[j4 * 4 + 3] += kd1 * v4.w;
            }
        }
        uint32_t* Breg = smem + (dp >> 4) * STGW + AWORDS;
#pragma unroll
        for (int j = 0; j < 8; j++) {
            sw_store_w(Breg, e0 + j, dp & 15, pack_h2(m0[j], m1[j]));
        }
    }
    __syncthreads();

    // apply: acc = q @ M over K=64 (stages 0,1)
#pragma unroll
    for (int mt = 0; mt < 2; mt++)
#pragma unroll
        for (int nt = 0; nt < 4; nt++)
#pragma unroll
            for (int i = 0; i < 4; i++) cacc[mt][nt][i] = 0.0f;

    mma_stage(smem_s + 0 * STGB, offA, offB, cacc);
    mma_stage(smem_s + 1 * STGB, offA, offB, cacc);

    // epilogue: out = tok + acc (exact fp32 residual)
#pragma unroll
    for (int mt = 0; mt < 2; mt++) {
#pragma unroll
        for (int nt = 0; nt < 4; nt++) {
            int row = row0 + warp_m * 32 + mt * 16 + gid;
            int col = col0 + warp_n * 32 + nt * 8 + c4 * 2;
            size_t a0 = (size_t)row * D_ + col;
            size_t a1 = (size_t)(row + 8) * D_ + col;
            float2 x0 = *reinterpret_cast<const float2*>(tok + a0);
            float2 x1 = *reinterpret_cast<const float2*>(tok + a1);
            *reinterpret_cast<float2*>(out + a0) =
                make_float2(cacc[mt][nt][0] + x0.x, cacc[mt][nt][1] + x0.y);
            *reinterpret_cast<float2*>(out + a1) =
                make_float2(cacc[mt][nt][2] + x1.x, cacc[mt][nt][3] + x1.y);
        }
    }
}

// -------------------- launch --------------------
extern "C" void kernel_launch(void* const* d_in, const int* in_sizes, int n_in,
                              void* d_out, int out_size) {
    const int*   spk = (const int*)d_in[1];
    const float* tok = (const float*)d_in[2];
    const float* edu = (const float*)d_in[3];
    const float* Wk  = (const float*)d_in[4];
    const float* Wv  = (const float*)d_in[5];
    const float* Wq  = (const float*)d_in[6];
    float* out = (float*)d_out;

    float* p_kvproj; cudaGetSymbolAddress((void**)&p_kvproj, g_kvproj);

    cudaFuncSetAttribute(qgemm_fused_kernel,
                         cudaFuncAttributeMaxDynamicSharedMemorySize, SMEM_BYTES);

    // 0) prep: kvproj (192 blocks) + fp16 convert of tok/Wq (12576 blocks), one launch
    {
        const size_t total = (size_t)B_ * T_ * L_ * D_ + (size_t)D_ * D_;
        int conv_blocks = (int)(total / (256 * 8));   // 12576, exact
        prep_kernel<<<KV_BLOCKS + conv_blocks, 256>>>(edu, Wk, Wv, p_kvproj, tok, Wq);
    }

    // 1) fused q projection + M build + apply + residual
    {
        dim3 grid(H_, B_ * T_);                       // (12, 256)
        qgemm_fused_kernel<<<grid, 256, SMEM_BYTES>>>(tok, spk, out);
    }
}

// round 13
// speedup vs baseline: 1.1319x; 1.1238x over previous
#include <cuda_runtime.h>
#include <cuda_fp16.h>
#include <cstdint>

// Problem shapes (fixed per reference)
#define B_  4
#define T_  64
#define L_  128
#define D_  768
#define H_  12
#define HD_ 64   // head dim

// -------------------- scratch (device globals; no allocation) --------------------
__device__ float  g_kvproj[B_ * T_ * 2 * D_];            // fp32 k|v rows=(b,t)
__device__ __half g_tokh[(size_t)B_ * T_ * L_ * D_];     // fp16 token embeddings
__device__ __half g_Wqh[D_ * D_];                        // fp16 Wq

__device__ __forceinline__ uint32_t pack_h2(float lo, float hi) {
    __half2 h = __floats2half2_rn(lo, hi);
    return *reinterpret_cast<uint32_t*>(&h);
}

// -------------------- prep kernel: kvproj (blocks 0..191) + fp16 convert (rest) --------------------
// kvproj: C[256,1536] = edu @ concat(Wk,Wv)^T, BM=32 BN=64 BK=32.
// tofp16: tok (25.2M) then Wq (0.59M), 2048 fp32 per block.
#define KV_BLOCKS 192

__global__ __launch_bounds__(256)
void prep_kernel(const float* __restrict__ edu, const float* __restrict__ Wk,
                 const float* __restrict__ Wv, float* __restrict__ C,
                 const float* __restrict__ tok, const float* __restrict__ Wq) {
    const int tid = threadIdx.x;

    if (blockIdx.x >= KV_BLOCKS) {
        // ---- fp32 -> fp16 streaming convert ----
        const size_t NT = (size_t)B_ * T_ * L_ * D_;
        size_t i = ((size_t)(blockIdx.x - KV_BLOCKS) * 256 + tid) * 8;
        if (i < NT) {
            float4 a = *reinterpret_cast<const float4*>(tok + i);
            float4 b = *reinterpret_cast<const float4*>(tok + i + 4);
            uint4 o;
            o.x = pack_h2(a.x, a.y); o.y = pack_h2(a.z, a.w);
            o.z = pack_h2(b.x, b.y); o.w = pack_h2(b.z, b.w);
            *reinterpret_cast<uint4*>(g_tokh + i) = o;
        } else {
            size_t j = i - NT;
            if (j < (size_t)D_ * D_) {
                float4 a = *reinterpret_cast<const float4*>(Wq + j);
                float4 b = *reinterpret_cast<const float4*>(Wq + j + 4);
                uint4 o;
                o.x = pack_h2(a.x, a.y); o.y = pack_h2(a.z, a.w);
                o.z = pack_h2(b.x, b.y); o.w = pack_h2(b.z, b.w);
                *reinterpret_cast<uint4*>(g_Wqh + j) = o;
            }
        }
        return;
    }

    // ---- kv projection ----
    __shared__ float As[32][33];
    __shared__ float Bs[32][68];

    const int K = D_, N = 2 * D_;
    const int tx  = tid & 15;
    const int ty  = tid >> 4;
    const int row0 = (blockIdx.x / 24) * 32;
    const int col0 = (blockIdx.x % 24) * 64;

    const float* Bbase = (col0 < D_) ? Wk : Wv;
    const int    bn0   = (col0 < D_) ? col0 : (col0 - D_);

    float acc[2][4];
#pragma unroll
    for (int i = 0; i < 2; i++)
#pragma unroll
        for (int j = 0; j < 4; j++) acc[i][j] = 0.0f;

    for (int k0 = 0; k0 < K; k0 += 32) {
        {
            int r = tid >> 3, kq = tid & 7;
            float4 v = *reinterpret_cast<const float4*>(&edu[(size_t)(row0 + r) * K + k0 + kq * 4]);
            As[kq * 4 + 0][r] = v.x; As[kq * 4 + 1][r] = v.y;
            As[kq * 4 + 2][r] = v.z; As[kq * 4 + 3][r] = v.w;
        }
#pragma unroll
        for (int i = 0; i < 2; i++) {
            int idx = tid + i * 256;
            int r = idx >> 3, kq = idx & 7;
            float4 v = *reinterpret_cast<const float4*>(&Bbase[(size_t)(bn0 + r) * K + k0 + kq * 4]);
            Bs[kq * 4 + 0][r] = v.x; Bs[kq * 4 + 1][r] = v.y;
            Bs[kq * 4 + 2][r] = v.z; Bs[kq * 4 + 3][r] = v.w;
        }
        __syncthreads();

#pragma unroll
        for (int kk = 0; kk < 32; kk++) {
            float ar[2];
            ar[0] = As[kk][ty * 2 + 0];
            ar[1] = As[kk][ty * 2 + 1];
            float4 b4 = *reinterpret_cast<const float4*>(&Bs[kk][tx * 4]);
            acc[0][0] += ar[0] * b4.x; acc[0][1] += ar[0] * b4.y;
            acc[0][2] += ar[0] * b4.z; acc[0][3] += ar[0] * b4.w;
            acc[1][0] += ar[1] * b4.x; acc[1][1] += ar[1] * b4.y;
            acc[1][2] += ar[1] * b4.z; acc[1][3] += ar[1] * b4.w;
        }
        __syncthreads();
    }

#pragma unroll
    for (int i = 0; i < 2; i++) {
        float4 v = make_float4(acc[i][0], acc[i][1], acc[i][2], acc[i][3]);
        *reinterpret_cast<float4*>(&C[(size_t)(row0 + ty * 2 + i) * N + col0 + tx * 4]) = v;
    }
}

// -------------------- fused q-projection + M build + apply --------------------
// cp.async 3-stage pipeline, fp16 smem, 16B-granular swizzle, ldmatrix fragments.
// Swizzle: logical unit u (16B) of row r placed at u ^ swz(r), swz(r) = (r&3) ^ ((r>>2)&1).

#define QBM 128
#define QBN 64
#define STGB 12288                          // bytes per stage
#define STGW 3072                           // words per stage
#define ABYTES 8192                         // A region bytes
#define AWORDS 2048
#define KBW  (3 * STGW)                     // kb word offset
#define VBW  (KBW + T_ * HD_)
#define SPKW (VBW + T_ * HD_)
#define SMEM_WORDS (SPKW + T_)
#define SMEM_BYTES (SMEM_WORDS * 4)         // 69888 B

__device__ __forceinline__ int swz(int r) { return (r & 3) ^ ((r >> 2) & 1); }

__device__ __forceinline__ void cp16(uint32_t dst, const void* src) {
    asm volatile("cp.async.ca.shared.global [%0], [%1], 16;" :: "r"(dst), "l"(src));
}
#define CP_COMMIT() asm volatile("cp.async.commit_group;")
template <int N> __device__ __forceinline__ void cp_wait() {
    asm volatile("cp.async.wait_group %0;" :: "n"(N));
}

__device__ __forceinline__ void ldsm4(uint32_t& r0, uint32_t& r1, uint32_t& r2, uint32_t& r3,
                                      uint32_t addr) {
    asm volatile("ldmatrix.sync.aligned.m8n8.x4.shared.b16 {%0,%1,%2,%3}, [%4];"
                 : "=r"(r0), "=r"(r1), "=r"(r2), "=r"(r3) : "r"(addr));
}

__device__ __forceinline__ void mma_f16(float c[4], uint32_t a0, uint32_t a1,
                                        uint32_t a2, uint32_t a3,
                                        uint32_t b0, uint32_t b1) {
    asm volatile(
        "mma.sync.aligned.m16n8k16.row.col.f32.f16.f16.f32 "
        "{%0,%1,%2,%3}, {%4,%5,%6,%7}, {%8,%9}, {%0,%1,%2,%3};"
        : "+f"(c[0]), "+f"(c[1]), "+f"(c[2]), "+f"(c[3])
        : "r"(a0), "r"(a1), "r"(a2), "r"(a3), "r"(b0), "r"(b1));
}

// phase-2 scalar word store into swizzled layout: word w (0..15) of row r
__device__ __forceinline__ void sw_store_w(uint32_t* region, int r, int w, uint32_t v) {
    region[r * 16 + ((((w >> 2) ^ swz(r)) << 2) | (w & 3))] = v;
}

// one BK=32 stage of mma via ldmatrix; offsets are byte offsets relative to stage base
__device__ __forceinline__ void mma_stage(uint32_t sbase, const uint32_t offA[2][2],
                                          const uint32_t offB[2][2], float acc[2][4][4]) {
#pragma unroll
    for (int ks = 0; ks < 2; ks++) {
        uint32_t a[2][4], bb[2][4];
#pragma unroll
        for (int mt = 0; mt < 2; mt++)
            ldsm4(a[mt][0], a[mt][1], a[mt][2], a[mt][3], sbase + offA[mt][ks]);
#pragma unroll
        for (int P = 0; P < 2; P++)
            ldsm4(bb[P][0], bb[P][1], bb[P][2], bb[P][3], sbase + offB[P][ks]);
#pragma unroll
        for (int mt = 0; mt < 2; mt++)
#pragma unroll
            for (int nt = 0; nt < 4; nt++) {
                const int P = nt >> 1, pp = nt & 1;
                mma_f16(acc[mt][nt], a[mt][0], a[mt][1], a[mt][2], a[mt][3],
                        bb[P][2 * pp], bb[P][2 * pp + 1]);
            }
    }
}

__global__ __launch_bounds__(256, 2)
void qgemm_fused_kernel(const float* __restrict__ tok, const int* __restrict__ spk,
                        float* __restrict__ out) {
    extern __shared__ uint32_t smem[];
    const uint32_t smem_s = (uint32_t)__cvta_generic_to_shared(smem);

    const int tid  = threadIdx.x;
    const int warp = tid >> 5;
    const int lane = tid & 31;
    const int gid  = lane >> 2;
    const int c4   = lane & 3;
    const int warp_m = warp & 3;
    const int warp_n = warp >> 2;

    const int hblk = blockIdx.x;
    const int bt   = blockIdx.y;
    const int b    = bt >> 6;
    const int tloc = bt & 63;
    const int row0 = bt * QBM;
    const int col0 = hblk * QBN;

    // ---- cp.async source/dest (relative byte offsets within stage) ----
    const int rA0 = tid >> 2,          uA0 = tid & 3;
    const int rA1 = (tid + 256) >> 2,  uA1 = tid & 3;   // idx+256: u unchanged, r += 64
    const int rB  = tid >> 2,          uB  = tid & 3;
    const __half* gA0 = g_tokh + (size_t)(row0 + rA0) * D_ + uA0 * 8;
    const __half* gA1 = g_tokh + (size_t)(row0 + rA1) * D_ + uA1 * 8;
    const __half* gB  = g_Wqh  + (size_t)(col0 + rB) * D_ + uB * 8;
    const uint32_t dA0 = rA0 * 64 + ((uA0 ^ swz(rA0)) << 4);
    const uint32_t dA1 = rA1 * 64 + ((uA1 ^ swz(rA1)) << 4);
    const uint32_t dB  = ABYTES + rB * 64 + ((uB ^ swz(rB)) << 4);

    // ---- ldmatrix lane offsets (relative byte offsets within stage) ----
    uint32_t offA[2][2], offB[2][2];
#pragma unroll
    for (int mt = 0; mt < 2; mt++)
#pragma unroll
        for (int ks = 0; ks < 2; ks++) {
            int r = warp_m * 32 + mt * 16 + (lane & 7) + ((lane >> 3) & 1) * 8;
            int u = 2 * ks + (lane >> 4);
            offA[mt][ks] = r * 64 + ((u ^ swz(r)) << 4);
        }
#pragma unroll
    for (int P = 0; P < 2; P++)
#pragma unroll
        for (int ks = 0; ks < 2; ks++) {
            int n = warp_n * 32 + P * 16 + (lane & 7) + ((lane >> 4) & 1) * 8;
            int u = 2 * ks + ((lane >> 3) & 1);
            offB[P][ks] = ABYTES + n * 64 + ((u ^ swz(n)) << 4);
        }

    float cacc[2][4][4];
#pragma unroll
    for (int mt = 0; mt < 2; mt++)
#pragma unroll
        for (int nt = 0; nt < 4; nt++)
#pragma unroll
            for (int i = 0; i < 4; i++) cacc[mt][nt][i] = 0.0f;

    // ---- prologue: stages 0,1 in flight ----
    {
        cp16(smem_s + 0 * STGB + dA0, gA0 + 0);
        cp16(smem_s + 0 * STGB + dA1, gA1 + 0);
        cp16(smem_s + 0 * STGB + dB,  gB  + 0);
        CP_COMMIT();
        cp16(smem_s + 1 * STGB + dA0, gA0 + 32);
        cp16(smem_s + 1 * STGB + dA1, gA1 + 32);
        cp16(smem_s + 1 * STGB + dB,  gB  + 32);
        CP_COMMIT();
    }

    // ---- main loop: 24 iterations, 3-stage pipeline, 1 barrier/iter ----
#pragma unroll
    for (int it = 0; it < 24; it++) {
        if (it == 23) cp_wait<0>(); else cp_wait<1>();
        __syncthreads();
        if (it + 2 < 24) {
            const uint32_t sb = smem_s + ((it + 2) % 3) * STGB;
            const int k = (it + 2) * 32;
            cp16(sb + dA0, gA0 + k);
            cp16(sb + dA1, gA1 + k);
            cp16(sb + dB,  gB  + k);
            CP_COMMIT();
        }
        mma_stage(smem_s + (it % 3) * STGB, offA, offB, cacc);
    }

    // ---------------- phase 2: build M in-block, then out = tok + q @ M ----------------
    float* kbs  = reinterpret_cast<float*>(smem + KBW);
    float* vbs  = reinterpret_cast<float*>(smem + VBW);
    int*   sspk = reinterpret_cast<int*>(smem + SPKW);

    // stage k,v for (b,h) into disjoint scratch (safe pre-sync)
    {
        const float* kvb = g_kvproj + (size_t)(b * T_) * (2 * D_);
#pragma unroll
        for (int i = 0; i < 4; i++) {
            int idx = tid + i * 256;
            int u = idx >> 4, dq = idx & 15;
            *reinterpret_cast<float4*>(&kbs[u * HD_ + dq * 4]) =
                *reinterpret_cast<const float4*>(&kvb[(size_t)u * (2 * D_) + hblk * HD_ + dq * 4]);
            *reinterpret_cast<float4*>(&vbs[u * HD_ + dq * 4]) =
                *reinterpret_cast<const float4*>(&kvb[(size_t)u * (2 * D_) + D_ + hblk * HD_ + dq * 4]);
        }
        if (tid < T_) sspk[tid] = spk[b * T_ + tid];
    }

    // write q (fp16) into A-areas of stages 0/1 (k-col c: stage = c>>5).
    // Safe without extra barrier: stages 0,1 were last read by mma(21),(22),
    // complete before barrier(23) for all threads; concurrent mma(23) reads stage 2 only.
    {
        uint32_t* Areg = smem + warp_n * STGW;
#pragma unroll
        for (int mt = 0; mt < 2; mt++) {
#pragma unroll
            for (int nt = 0; nt < 4; nt++) {
                int r = warp_m * 32 + mt * 16 + gid;
                int w = nt * 4 + c4;                 // word within 32-col stage
                sw_store_w(Areg, r,     w, pack_h2(cacc[mt][nt][0], cacc[mt][nt][1]));
                sw_store_w(Areg, r + 8, w, pack_h2(cacc[mt][nt][2], cacc[mt][nt][3]));
            }
        }
    }
    __syncthreads();   // kv/spk visible; q writes done

    // build M[d][e] (fp32, ascending u); store M^T (fp16) into B-areas of stages 0/1
    {
        const int dp = tid >> 3;            // d0 = 2dp, d1 = 2dp+1
        const int e0 = (tid & 7) * 8;
        const int d0 = dp * 2;
        const int myspk = sspk[tloc];
        float m0[8], m1[8];
#pragma unroll
        for (int j = 0; j < 8; j++) { m0[j] = 0.0f; m1[j] = 0.0f; }

        for (int u = 0; u <= tloc; u++) {
            if (sspk[u] != myspk) continue;
            float kd0 = kbs[u * HD_ + d0];
            float kd1 = kbs[u * HD_ + d0 + 1];
#pragma unroll
            for (int j4 = 0; j4 < 2; j4++) {
                float4 v4 = *reinterpret_cast<const float4*>(&vbs[u * HD_ + e0 + j4 * 4]);
                m0[j4 * 4 + 0] += kd0 * v4.x; m1[j4 * 4 + 0] += kd1 * v4.x;
                m0[j4 * 4 + 1] += kd0 * v4.y; m1[j4 * 4 + 1] += kd1 * v4.y;
                m0[j4 * 4 + 2] += kd0 * v4.z; m1[j4 * 4 + 2] += kd1 * v4.z;
                m0[j4 * 4 + 3] += kd0 * v4.w; m1[j4 * 4 + 3] += kd1 * v4.w;
            }
        }
        uint32_t* Breg = smem + (dp >> 4) * STGW + AWORDS;
#pragma unroll
        for (int j = 0; j < 8; j++) {
            sw_store_w(Breg, e0 + j, dp & 15, pack_h2(m0[j], m1[j]));
        }
    }
    __syncthreads();

    // apply: acc = q @ M over K=64 (stages 0,1)
#pragma unroll
    for (int mt = 0; mt < 2; mt++)
#pragma unroll
        for (int nt = 0; nt < 4; nt++)
#pragma unroll
            for (int i = 0; i < 4; i++) cacc[mt][nt][i] = 0.0f;

    mma_stage(smem_s + 0 * STGB, offA, offB, cacc);
    mma_stage(smem_s + 1 * STGB, offA, offB, cacc);

    // epilogue: out = tok + acc (exact fp32 residual)
#pragma unroll
    for (int mt = 0; mt < 2; mt++) {
#pragma unroll
        for (int nt = 0; nt < 4; nt++) {
            int row = row0 + warp_m * 32 + mt * 16 + gid;
            int col = col0 + warp_n * 32 + nt * 8 + c4 * 2;
            size_t a0 = (size_t)row * D_ + col;
            size_t a1 = (size_t)(row + 8) * D_ + col;
            float2 x0 = *reinterpret_cast<const float2*>(tok + a0);
            float2 x1 = *reinterpret_cast<const float2*>(tok + a1);
            *reinterpret_cast<float2*>(out + a0) =
                make_float2(cacc[mt][nt][0] + x0.x, cacc[mt][nt][1] + x0.y);
            *reinterpret_cast<float2*>(out + a1) =
                make_float2(cacc[mt][nt][2] + x1.x, cacc[mt][nt][3] + x1.y);
        }
    }
}

// -------------------- launch --------------------
extern "C" void kernel_launch(void* const* d_in, const int* in_sizes, int n_in,
                              void* d_out, int out_size) {
    const int*   spk = (const int*)d_in[1];
    const float* tok = (const float*)d_in[2];
    const float* edu = (const float*)d_in[3];
    const float* Wk  = (const float*)d_in[4];
    const float* Wv  = (const float*)d_in[5];
    const float* Wq  = (const float*)d_in[6];
    float* out = (float*)d_out;

    float* p_kvproj; cudaGetSymbolAddress((void**)&p_kvproj, g_kvproj);

    cudaFuncSetAttribute(qgemm_fused_kernel,
                         cudaFuncAttributeMaxDynamicSharedMemorySize, SMEM_BYTES);

    // 0) prep: kvproj (192 blocks) + fp16 convert of tok/Wq (12576 blocks), one launch
    {
        const size_t total = (size_t)B_ * T_ * L_ * D_ + (size_t)D_ * D_;
        int conv_blocks = (int)(total / (256 * 8));   // 12576, exact
        prep_kernel<<<KV_BLOCKS + conv_blocks, 256>>>(edu, Wk, Wv, p_kvproj, tok, Wq);
    }

    // 1) fused q projection + M build + apply + residual
    {
        dim3 grid(H_, B_ * T_);                       // (12, 256)
        qgemm_fused_kernel<<<grid, 256, SMEM_BYTES>>>(tok, spk, out);
    }
}

// round 14
// speedup vs baseline: 1.2199x; 1.0778x over previous
#include <cuda_runtime.h>
#include <cuda_fp16.h>
#include <cstdint>

// Problem shapes (fixed per reference)
#define B_  4
#define T_  64
#define L_  128
#define D_  768
#define H_  12
#define HD_ 64   // head dim

// -------------------- scratch (device globals; no allocation) --------------------
__device__ float  g_kvproj[B_ * T_ * 2 * D_];            // fp32 k|v rows=(b,t)
__device__ __half g_tokh[(size_t)B_ * T_ * L_ * D_];     // fp16 token embeddings
__device__ __half g_Wqh[D_ * D_];                        // fp16 Wq

__device__ __forceinline__ uint32_t pack_h2(float lo, float hi) {
    __half2 h = __floats2half2_rn(lo, hi);
    return *reinterpret_cast<uint32_t*>(&h);
}

// -------------------- prep kernel: kvproj (blocks 0..191) + fp16 convert (rest) --------------------
#define KV_BLOCKS 192

__global__ __launch_bounds__(256)
void prep_kernel(const float* __restrict__ edu, const float* __restrict__ Wk,
                 const float* __restrict__ Wv, float* __restrict__ C,
                 const float* __restrict__ tok, const float* __restrict__ Wq) {
    const int tid = threadIdx.x;

    if (blockIdx.x >= KV_BLOCKS) {
        const size_t NT = (size_t)B_ * T_ * L_ * D_;
        size_t i = ((size_t)(blockIdx.x - KV_BLOCKS) * 256 + tid) * 8;
        if (i < NT) {
            float4 a = *reinterpret_cast<const float4*>(tok + i);
            float4 b = *reinterpret_cast<const float4*>(tok + i + 4);
            uint4 o;
            o.x = pack_h2(a.x, a.y); o.y = pack_h2(a.z, a.w);
            o.z = pack_h2(b.x, b.y); o.w = pack_h2(b.z, b.w);
            *reinterpret_cast<uint4*>(g_tokh + i) = o;
        } else {
            size_t j = i - NT;
            if (j < (size_t)D_ * D_) {
                float4 a = *reinterpret_cast<const float4*>(Wq + j);
                float4 b = *reinterpret_cast<const float4*>(Wq + j + 4);
                uint4 o;
                o.x = pack_h2(a.x, a.y); o.y = pack_h2(a.z, a.w);
                o.z = pack_h2(b.x, b.y); o.w = pack_h2(b.z, b.w);
                *reinterpret_cast<uint4*>(g_Wqh + j) = o;
            }
        }
        return;
    }

    __shared__ float As[32][33];
    __shared__ float Bs[32][68];

    const int K = D_, N = 2 * D_;
    const int tx  = tid & 15;
    const int ty  = tid >> 4;
    const int row0 = (blockIdx.x / 24) * 32;
    const int col0 = (blockIdx.x % 24) * 64;

    const float* Bbase = (col0 < D_) ? Wk : Wv;
    const int    bn0   = (col0 < D_) ? col0 : (col0 - D_);

    float acc[2][4];
#pragma unroll
    for (int i = 0; i < 2; i++)
#pragma unroll
        for (int j = 0; j < 4; j++) acc[i][j] = 0.0f;

    for (int k0 = 0; k0 < K; k0 += 32) {
        {
            int r = tid >> 3, kq = tid & 7;
            float4 v = *reinterpret_cast<const float4*>(&edu[(size_t)(row0 + r) * K + k0 + kq * 4]);
            As[kq * 4 + 0][r] = v.x; As[kq * 4 + 1][r] = v.y;
            As[kq * 4 + 2][r] = v.z; As[kq * 4 + 3][r] = v.w;
        }
#pragma unroll
        for (int i = 0; i < 2; i++) {
            int idx = tid + i * 256;
            int r = idx >> 3, kq = idx & 7;
            float4 v = *reinterpret_cast<const float4*>(&Bbase[(size_t)(bn0 + r) * K + k0 + kq * 4]);
            Bs[kq * 4 + 0][r] = v.x; Bs[kq * 4 + 1][r] = v.y;
            Bs[kq * 4 + 2][r] = v.z; Bs[kq * 4 + 3][r] = v.w;
        }
        __syncthreads();

#pragma unroll
        for (int kk = 0; kk < 32; kk++) {
            float ar[2];
            ar[0] = As[kk][ty * 2 + 0];
            ar[1] = As[kk][ty * 2 + 1];
            float4 b4 = *reinterpret_cast<const float4*>(&Bs[kk][tx * 4]);
            acc[0][0] += ar[0] * b4.x; acc[0][1] += ar[0] * b4.y;
            acc[0][2] += ar[0] * b4.z; acc[0][3] += ar[0] * b4.w;
            acc[1][0] += ar[1] * b4.x; acc[1][1] += ar[1] * b4.y;
            acc[1][2] += ar[1] * b4.z; acc[1][3] += ar[1] * b4.w;
        }
        __syncthreads();
    }

#pragma unroll
    for (int i = 0; i < 2; i++) {
        float4 v = make_float4(acc[i][0], acc[i][1], acc[i][2], acc[i][3]);
        *reinterpret_cast<float4*>(&C[(size_t)(row0 + ty * 2 + i) * N + col0 + tx * 4]) = v;
    }
}

// -------------------- fused q-projection + M build + apply (128x128 tile, 2 heads) --------------------
// Block (x = head-pair, y = bt): q[128x128] = tok_tile @ Wq[2 heads]^T (K=768, 4-stage cp.async),
// then M0,M1 built in-block (fp32), apply as q @ blockdiag(M0,M1) (zero off-blocks), residual.
// Swizzle: 16B unit u of row r at u ^ swz(r), swz(r) = (r&3) ^ ((r>>2)&1).

#define QBM 128
#define QBN 128
#define NSTG 4
#define STGB 16384                          // bytes per stage (A 8192 + B 8192)
#define STGW 4096                           // words per stage
#define ABYTES 8192
#define AWORDS 2048
#define KBW  (NSTG * STGW)                  // 16384: kbs [2][64][64] fp32
#define VBW  (KBW + 2 * T_ * HD_)           // 24576: vbs [2][64][64]
#define SPKW (VBW + 2 * T_ * HD_)           // 32768
#define SMEM_WORDS (SPKW + T_)
#define SMEM_BYTES (SMEM_WORDS * 4)         // 131328 B

__device__ __forceinline__ int swz(int r) { return (r & 3) ^ ((r >> 2) & 1); }

__device__ __forceinline__ void cp16(uint32_t dst, const void* src) {
    asm volatile("cp.async.ca.shared.global [%0], [%1], 16;" :: "r"(dst), "l"(src));
}
#define CP_COMMIT() asm volatile("cp.async.commit_group;")
template <int N> __device__ __forceinline__ void cp_wait() {
    asm volatile("cp.async.wait_group %0;" :: "n"(N));
}

__device__ __forceinline__ void ldsm4(uint32_t& r0, uint32_t& r1, uint32_t& r2, uint32_t& r3,
                                      uint32_t addr) {
    asm volatile("ldmatrix.sync.aligned.m8n8.x4.shared.b16 {%0,%1,%2,%3}, [%4];"
                 : "=r"(r0), "=r"(r1), "=r"(r2), "=r"(r3) : "r"(addr));
}

__device__ __forceinline__ void mma_f16(float c[4], uint32_t a0, uint32_t a1,
                                        uint32_t a2, uint32_t a3,
                                        uint32_t b0, uint32_t b1) {
    asm volatile(
        "mma.sync.aligned.m16n8k16.row.col.f32.f16.f16.f32 "
        "{%0,%1,%2,%3}, {%4,%5,%6,%7}, {%8,%9}, {%0,%1,%2,%3};"
        : "+f"(c[0]), "+f"(c[1]), "+f"(c[2]), "+f"(c[3])
        : "r"(a0), "r"(a1), "r"(a2), "r"(a3), "r"(b0), "r"(b1));
}

// phase-2 scalar word store into swizzled layout: word w (0..15) of row r
__device__ __forceinline__ void sw_store_w(uint32_t* region, int r, int w, uint32_t v) {
    region[r * 16 + ((((w >> 2) ^ swz(r)) << 2) | (w & 3))] = v;
}

// one BK=32 stage: warp tile 32x64, 32 mma per warp
__device__ __forceinline__ void mma_stage(uint32_t sbase, const uint32_t offA[2][2],
                                          const uint32_t offB[4][2], float acc[2][8][4]) {
#pragma unroll
    for (int ks = 0; ks < 2; ks++) {
        uint32_t a[2][4], bb[4][4];
#pragma unroll
        for (int mt = 0; mt < 2; mt++)
            ldsm4(a[mt][0], a[mt][1], a[mt][2], a[mt][3], sbase + offA[mt][ks]);
#pragma unroll
        for (int P = 0; P < 4; P++)
            ldsm4(bb[P][0], bb[P][1], bb[P][2], bb[P][3], sbase + offB[P][ks]);
#pragma unroll
        for (int mt = 0; mt < 2; mt++)
#pragma unroll
            for (int nt = 0; nt < 8; nt++) {
                const int P = nt >> 1, pp = nt & 1;
                mma_f16(acc[mt][nt], a[mt][0], a[mt][1], a[mt][2], a[mt][3],
                        bb[P][2 * pp], bb[P][2 * pp + 1]);
            }
    }
}

__global__ __launch_bounds__(256, 1)
void qgemm_fused_kernel(const float* __restrict__ tok, const int* __restrict__ spk,
                        float* __restrict__ out) {
    extern __shared__ uint32_t smem[];
    const uint32_t smem_s = (uint32_t)__cvta_generic_to_shared(smem);

    const int tid  = threadIdx.x;
    const int warp = tid >> 5;
    const int lane = tid & 31;
    const int gid  = lane >> 2;
    const int c4   = lane & 3;
    const int warp_m = warp & 3;     // 4 x 32-row positions
    const int warp_n = warp >> 2;    // 2 x 64-col positions

    const int hpair = blockIdx.x;    // 0..5 -> heads 2*hpair, 2*hpair+1
    const int bt    = blockIdx.y;
    const int b     = bt >> 6;
    const int tloc  = bt & 63;
    const int row0  = bt * QBM;
    const int col0  = hpair * QBN;

    // ---- cp.async source/dest ----
    const int rL = tid >> 2, uL = tid & 3;
    const __half* gA0 = g_tokh + (size_t)(row0 + rL) * D_ + uL * 8;
    const __half* gA1 = gA0 + (size_t)64 * D_;
    const __half* gB0 = g_Wqh + (size_t)(col0 + rL) * D_ + uL * 8;
    const __half* gB1 = gB0 + (size_t)64 * D_;
    const uint32_t dA0 = rL * 64 + ((uL ^ swz(rL)) << 4);
    const uint32_t dA1 = dA0 + 64 * 64;          // swz(r+64)==swz(r)
    const uint32_t dB0 = ABYTES + dA0;
    const uint32_t dB1 = ABYTES + dA1;

    // ---- ldmatrix lane offsets ----
    uint32_t offA[2][2], offB[4][2];
#pragma unroll
    for (int mt = 0; mt < 2; mt++)
#pragma unroll
        for (int ks = 0; ks < 2; ks++) {
            int r = warp_m * 32 + mt * 16 + (lane & 7) + ((lane >> 3) & 1) * 8;
            int u = 2 * ks + (lane >> 4);
            offA[mt][ks] = r * 64 + ((u ^ swz(r)) << 4);
        }
#pragma unroll
    for (int P = 0; P < 4; P++)
#pragma unroll
        for (int ks = 0; ks < 2; ks++) {
            int n = warp_n * 64 + P * 16 + (lane & 7) + ((lane >> 4) & 1) * 8;
            int u = 2 * ks + ((lane >> 3) & 1);
            offB[P][ks] = ABYTES + n * 64 + ((u ^ swz(n)) << 4);
        }

    float cacc[2][8][4];
#pragma unroll
    for (int mt = 0; mt < 2; mt++)
#pragma unroll
        for (int nt = 0; nt < 8; nt++)
#pragma unroll
            for (int i = 0; i < 4; i++) cacc[mt][nt][i] = 0.0f;

    // ---- prologue: stages 0,1,2 in flight ----
#pragma unroll
    for (int s = 0; s < 3; s++) {
        const uint32_t sb = smem_s + s * STGB;
        cp16(sb + dA0, gA0 + s * 32);
        cp16(sb + dA1, gA1 + s * 32);
        cp16(sb + dB0, gB0 + s * 32);
        cp16(sb + dB1, gB1 + s * 32);
        CP_COMMIT();
    }

    // ---- main loop: 24 iterations, 4-stage pipeline ----
#pragma unroll
    for (int it = 0; it < 24; it++) {
        if (it < 22) cp_wait<2>();
        else if (it == 22) cp_wait<1>();
        else cp_wait<0>();
        __syncthreads();
        if (it + 3 < 24) {
            const uint32_t sb = smem_s + ((it + 3) & 3) * STGB;
            const int k = (it + 3) * 32;
            cp16(sb + dA0, gA0 + k);
            cp16(sb + dA1, gA1 + k);
            cp16(sb + dB0, gB0 + k);
            cp16(sb + dB1, gB1 + k);
            CP_COMMIT();
        }
        mma_stage(smem_s + (it & 3) * STGB, offA, offB, cacc);
    }

    // ---------------- phase 2 ----------------
    float* kbs  = reinterpret_cast<float*>(smem + KBW);   // [2][64][64]
    float* vbs  = reinterpret_cast<float*>(smem + VBW);   // [2][64][64]
    int*   sspk = reinterpret_cast<int*>(smem + SPKW);

    // stage k,v for (b, 2 heads) into disjoint scratch (safe pre-barrier)
    {
        const float* kvb = g_kvproj + (size_t)(b * T_) * (2 * D_);
#pragma unroll
        for (int i = 0; i < 16; i++) {
            int idx = tid + i * 256;          // 0..4095 float4 slots
            int sel = idx >> 10;              // 0:k-h0 1:k-h1 2:v-h0 3:v-h1
            int s2  = idx & 1023;
            int u   = s2 >> 4, dq = s2 & 15;
            int h   = sel & 1, isV = sel >> 1;
            const float* src = kvb + (size_t)u * (2 * D_) + (size_t)isV * D_
                               + (2 * hpair + h) * HD_ + dq * 4;
            float* dst = (isV ? vbs : kbs) + h * 4096 + u * HD_ + dq * 4;
            *reinterpret_cast<float4*>(dst) = *reinterpret_cast<const float4*>(src);
        }
        if (tid < T_) sspk[tid] = spk[b * T_ + tid];
    }
    __syncthreads();   // mma(23) done everywhere; kv/spk visible

    // write q (fp16) into A-areas of all 4 stages: col c -> stage c>>5, word (c&31)>>1
    {
#pragma unroll
        for (int mt = 0; mt < 2; mt++) {
#pragma unroll
            for (int nt = 0; nt < 8; nt++) {
                int stage = warp_n * 2 + (nt >> 2);
                int w = (nt & 3) * 4 + c4;
                int r = warp_m * 32 + mt * 16 + gid;
                uint32_t* Areg = smem + stage * STGW;
                sw_store_w(Areg, r,     w, pack_h2(cacc[mt][nt][0], cacc[mt][nt][1]));
                sw_store_w(Areg, r + 8, w, pack_h2(cacc[mt][nt][2], cacc[mt][nt][3]));
            }
        }
    }

    // zero off-diagonal B blocks: stages 0,1 rows 64..127; stages 2,3 rows 0..63
    {
        int j0 = tid * 16;                    // 4096 words total
        int reg = j0 >> 10, off = j0 & 1023;
        uint32_t* p = smem + reg * STGW + AWORDS + ((reg < 2) ? 1024 : 0) + off;
#pragma unroll
        for (int i = 0; i < 4; i++)
            *reinterpret_cast<uint4*>(p + i * 4) = make_uint4(0, 0, 0, 0);
    }

    // build M[h][d][e] (fp32, ascending u); store M^T fp16 into B-areas
    {
        const int h  = tid >> 7;              // 0,1
        const int t7 = tid & 127;
        const int dp = t7 >> 2;               // 0..31  (d0=2dp)
        const int e0 = (t7 & 3) * 16;
        const int d0 = dp * 2;
        const int myspk = sspk[tloc];
        const float* kb = kbs + h * 4096;
        const float* vb = vbs + h * 4096;
        float m0[16], m1[16];
#pragma unroll
        for (int j = 0; j < 16; j++) { m0[j] = 0.0f; m1[j] = 0.0f; }

        for (int u = 0; u <= tloc; u++) {
            if (sspk[u] != myspk) continue;
            float kd0 = kb[u * HD_ + d0];
            float kd1 = kb[u * HD_ + d0 + 1];
#pragma unroll
            for (int j4 = 0; j4 < 4; j4++) {
                float4 v4 = *reinterpret_cast<const float4*>(&vb[u * HD_ + e0 + j4 * 4]);
                m0[j4 * 4 + 0] += kd0 * v4.x; m1[j4 * 4 + 0] += kd1 * v4.x;
                m0[j4 * 4 + 1] += kd0 * v4.y; m1[j4 * 4 + 1] += kd1 * v4.y;
                m0[j4 * 4 + 2] += kd0 * v4.z; m1[j4 * 4 + 2] += kd1 * v4.z;
                m0[j4 * 4 + 3] += kd0 * v4.w; m1[j4 * 4 + 3] += kd1 * v4.w;
            }
        }
        // head h occupies k rows h*64+d -> stage h*2 + (dp>>4), word dp&15, B row h*64+e
        uint32_t* Breg = smem + (h * 2 + (dp >> 4)) * STGW + AWORDS;
        const int nb = h * 64 + e0;
#pragma unroll
        for (int j = 0; j < 16; j++)
            sw_store_w(Breg, nb + j, dp & 15, pack_h2(m0[j], m1[j]));
    }
    __syncthreads();

    // apply: acc = q @ blockdiag(M0,M1) over K=128 (4 stages; off-blocks are exact zeros)
#pragma unroll
    for (int mt = 0; mt < 2; mt++)
#pragma unroll
        for (int nt = 0; nt < 8; nt++)
#pragma unroll
            for (int i = 0; i < 4; i++) cacc[mt][nt][i] = 0.0f;

#pragma unroll
    for (int s = 0; s < 4; s++)
        mma_stage(smem_s + s * STGB, offA, offB, cacc);

    // epilogue: out = tok + acc (exact fp32 residual)
#pragma unroll
    for (int mt = 0; mt < 2; mt++) {
#pragma unroll
        for (int nt = 0; nt < 8; nt++) {
            int row = row0 + warp_m * 32 + mt * 16 + gid;
            int col = col0 + warp_n * 64 + nt * 8 + c4 * 2;
            size_t a0 = (size_t)row * D_ + col;
            size_t a1 = (size_t)(row + 8) * D_ + col;
            float2 x0 = *reinterpret_cast<const float2*>(tok + a0);
            float2 x1 = *reinterpret_cast<const float2*>(tok + a1);
            *reinterpret_cast<float2*>(out + a0) =
                make_float2(cacc[mt][nt][0] + x0.x, cacc[mt][nt][1] + x0.y);
            *reinterpret_cast<float2*>(out + a1) =
                make_float2(cacc[mt][nt][2] + x1.x, cacc[mt][nt][3] + x1.y);
        }
    }
}

// -------------------- launch --------------------
extern "C" void kernel_launch(void* const* d_in, const int* in_sizes, int n_in,
                              void* d_out, int out_size) {
    const int*   spk = (const int*)d_in[1];
    const float* tok = (const float*)d_in[2];
    const float* edu = (const float*)d_in[3];
    const float* Wk  = (const float*)d_in[4];
    const float* Wv  = (const float*)d_in[5];
    const float* Wq  = (const float*)d_in[6];
    float* out = (float*)d_out;

    float* p_kvproj; cudaGetSymbolAddress((void**)&p_kvproj, g_kvproj);

    cudaFuncSetAttribute(qgemm_fused_kernel,
                         cudaFuncAttributeMaxDynamicSharedMemorySize, SMEM_BYTES);

    // 0) prep: kvproj (192 blocks) + fp16 convert of tok/Wq, one launch
    {
        const size_t total = (size_t)B_ * T_ * L_ * D_ + (size_t)D_ * D_;
        int conv_blocks = (int)(total / (256 * 8));   // 12576, exact
        prep_kernel<<<KV_BLOCKS + conv_blocks, 256>>>(edu, Wk, Wv, p_kvproj, tok, Wq);
    }

    // 1) fused q projection + M build + apply + residual (2 heads per block)
    {
        dim3 grid(H_ / 2, B_ * T_);                   // (6, 256)
        qgemm_fused_kernel<<<grid, 256, SMEM_BYTES>>>(tok, spk, out);
    }
}

// round 16
// speedup vs baseline: 1.2388x; 1.0155x over previous
#include <cuda_runtime.h>
#include <cuda_fp16.h>
#include <cstdint>

// Problem shapes (fixed per reference)
#define B_  4
#define T_  64
#define L_  128
#define D_  768
#define H_  12
#define HD_ 64   // head dim

// -------------------- scratch (device globals; no allocation) --------------------
__device__ float  g_kvproj[B_ * T_ * 2 * D_];            // fp32 k|v rows=(b,t)
__device__ __half g_tokh[(size_t)B_ * T_ * L_ * D_];     // fp16 token embeddings
__device__ __half g_Wqh[D_ * D_];                        // fp16 Wq

__device__ __forceinline__ uint32_t pack_h2(float lo, float hi) {
    __half2 h = __floats2half2_rn(lo, hi);
    return *reinterpret_cast<uint32_t*>(&h);
}

// -------------------- prep kernel: kvproj (blocks 0..191) + fp16 convert (rest) --------------------
#define KV_BLOCKS 192

__global__ __launch_bounds__(256)
void prep_kernel(const float* __restrict__ edu, const float* __restrict__ Wk,
                 const float* __restrict__ Wv, float* __restrict__ C,
                 const float* __restrict__ tok, const float* __restrict__ Wq) {
    const int tid = threadIdx.x;

    if (blockIdx.x >= KV_BLOCKS) {
        const size_t NT = (size_t)B_ * T_ * L_ * D_;
        size_t i = ((size_t)(blockIdx.x - KV_BLOCKS) * 256 + tid) * 8;
        if (i < NT) {
            float4 a = *reinterpret_cast<const float4*>(tok + i);
            float4 b = *reinterpret_cast<const float4*>(tok + i + 4);
            uint4 o;
            o.x = pack_h2(a.x, a.y); o.y = pack_h2(a.z, a.w);
            o.z = pack_h2(b.x, b.y); o.w = pack_h2(b.z, b.w);
            *reinterpret_cast<uint4*>(g_tokh + i) = o;
        } else {
            size_t j = i - NT;
            if (j < (size_t)D_ * D_) {
                float4 a = *reinterpret_cast<const float4*>(Wq + j);
                float4 b = *reinterpret_cast<const float4*>(Wq + j + 4);
                uint4 o;
                o.x = pack_h2(a.x, a.y); o.y = pack_h2(a.z, a.w);
                o.z = pack_h2(b.x, b.y); o.w = pack_h2(b.z, b.w);
                *reinterpret_cast<uint4*>(g_Wqh + j) = o;
            }
        }
        return;
    }

    __shared__ float As[32][33];
    __shared__ float Bs[32][68];

    const int K = D_, N = 2 * D_;
    const int tx  = tid & 15;
    const int ty  = tid >> 4;
    const int row0 = (blockIdx.x / 24) * 32;
    const int col0 = (blockIdx.x % 24) * 64;

    const float* Bbase = (col0 < D_) ? Wk : Wv;
    const int    bn0   = (col0 < D_) ? col0 : (col0 - D_);

    float acc[2][4];
#pragma unroll
    for (int i = 0; i < 2; i++)
#pragma unroll
        for (int j = 0; j < 4; j++) acc[i][j] = 0.0f;

    for (int k0 = 0; k0 < K; k0 += 32) {
        {
            int r = tid >> 3, kq = tid & 7;
            float4 v = *reinterpret_cast<const float4*>(&edu[(size_t)(row0 + r) * K + k0 + kq * 4]);
            As[kq * 4 + 0][r] = v.x; As[kq * 4 + 1][r] = v.y;
            As[kq * 4 + 2][r] = v.z; As[kq * 4 + 3][r] = v.w;
        }
#pragma unroll
        for (int i = 0; i < 2; i++) {
            int idx = tid + i * 256;
            int r = idx >> 3, kq = idx & 7;
            float4 v = *reinterpret_cast<const float4*>(&Bbase[(size_t)(bn0 + r) * K + k0 + kq * 4]);
            Bs[kq * 4 + 0][r] = v.x; Bs[kq * 4 + 1][r] = v.y;
            Bs[kq * 4 + 2][r] = v.z; Bs[kq * 4 + 3][r] = v.w;
        }
        __syncthreads();

#pragma unroll
        for (int kk = 0; kk < 32; kk++) {
            float ar[2];
            ar[0] = As[kk][ty * 2 + 0];
            ar[1] = As[kk][ty * 2 + 1];
            float4 b4 = *reinterpret_cast<const float4*>(&Bs[kk][tx * 4]);
            acc[0][0] += ar[0] * b4.x; acc[0][1] += ar[0] * b4.y;
            acc[0][2] += ar[0] * b4.z; acc[0][3] += ar[0] * b4.w;
            acc[1][0] += ar[1] * b4.x; acc[1][1] += ar[1] * b4.y;
            acc[1][2] += ar[1] * b4.z; acc[1][3] += ar[1] * b4.w;
        }
        __syncthreads();
    }

#pragma unroll
    for (int i = 0; i < 2; i++) {
        float4 v = make_float4(acc[i][0], acc[i][1], acc[i][2], acc[i][3]);
        *reinterpret_cast<float4*>(&C[(size_t)(row0 + ty * 2 + i) * N + col0 + tx * 4]) = v;
    }
}

// -------------------- fused kernel: 256x128 tile (2 turns x 2 heads) --------------------
// Block (x=hpair, y=btp): q[256x128] = tok rows @ Wq[2 heads]^T, K=768, 3-stage cp.async,
// warp tile 64x64 (8 warps, 4m x 2n). Then 4 M matrices (t0/t1 x h0/h1) built fp32 in-block,
// apply q @ blockdiag per row-half (warp_m<2 -> t0 B, else t1 B), fp32 residual epilogue.
// Swizzle: 16B unit u of row r at u ^ swz(r), swz(r) = (r&3) ^ ((r>>2)&1).

#define STAGEB 24576                        // A 16384 (256 rows x 64B) + B 8192 (128 rows)
#define ABW    16384
#define KB_OFF   73728                      // kbs [2][64][64] fp32 (32 KB); reused as apply-B
#define VB_OFF   106496                     // vbs [2][64][64] fp32 (32 KB)
#define SPK_OFF  139264                     // int[64]
#define SMEM_BYTES 139520

__device__ __forceinline__ int swz(int r) { return (r & 3) ^ ((r >> 2) & 1); }

__device__ __forceinline__ void cp16(uint32_t dst, const void* src) {
    asm volatile("cp.async.ca.shared.global [%0], [%1], 16;" :: "r"(dst), "l"(src));
}
#define CP_COMMIT() asm volatile("cp.async.commit_group;")
template <int N> __device__ __forceinline__ void cp_wait() {
    asm volatile("cp.async.wait_group %0;" :: "n"(N));
}

__device__ __forceinline__ void ldsm4(uint32_t& r0, uint32_t& r1, uint32_t& r2, uint32_t& r3,
                                      uint32_t addr) {
    asm volatile("ldmatrix.sync.aligned.m8n8.x4.shared.b16 {%0,%1,%2,%3}, [%4];"
                 : "=r"(r0), "=r"(r1), "=r"(r2), "=r"(r3) : "r"(addr));
}

__device__ __forceinline__ void mma_f16(float c[4], uint32_t a0, uint32_t a1,
                                        uint32_t a2, uint32_t a3,
                                        uint32_t b0, uint32_t b1) {
    asm volatile(
        "mma.sync.aligned.m16n8k16.row.col.f32.f16.f16.f32 "
        "{%0,%1,%2,%3}, {%4,%5,%6,%7}, {%8,%9}, {%0,%1,%2,%3};"
        : "+f"(c[0]), "+f"(c[1]), "+f"(c[2]), "+f"(c[3])
        : "r"(a0), "r"(a1), "r"(a2), "r"(a3), "r"(b0), "r"(b1));
}

// one BK=32 stage: warp tile 64x64, 64 mma per warp
__device__ __forceinline__ void mma_stage(uint32_t sbase, const uint32_t offA[4][2],
                                          const uint32_t offB[4][2], float acc[4][8][4]) {
#pragma unroll
    for (int ks = 0; ks < 2; ks++) {
        uint32_t a[4][4], bb[4][4];
#pragma unroll
        for (int mt = 0; mt < 4; mt++)
            ldsm4(a[mt][0], a[mt][1], a[mt][2], a[mt][3], sbase + offA[mt][ks]);
#pragma unroll
        for (int P = 0; P < 4; P++)
            ldsm4(bb[P][0], bb[P][1], bb[P][2], bb[P][3], sbase + offB[P][ks]);
#pragma unroll
        for (int mt = 0; mt < 4; mt++)
#pragma unroll
            for (int nt = 0; nt < 8; nt++) {
                const int P = nt >> 1, pp = nt & 1;
                mma_f16(acc[mt][nt], a[mt][0], a[mt][1], a[mt][2], a[mt][3],
                        bb[P][2 * pp], bb[P][2 * pp + 1]);
            }
    }
}

__global__ __launch_bounds__(256, 1)
void qgemm_fused_kernel(const float* __restrict__ tok, const int* __restrict__ spk,
                        float* __restrict__ out) {
    extern __shared__ uint32_t smem[];
    char* smemc = reinterpret_cast<char*>(smem);
    const uint32_t smem_s = (uint32_t)__cvta_generic_to_shared(smem);

    const int tid  = threadIdx.x;
    const int warp = tid >> 5;
    const int lane = tid & 31;
    const int gid  = lane >> 2;
    const int c4   = lane & 3;
    const int warp_m = warp & 3;     // 4 x 64-row blocks
    const int warp_n = warp >> 2;    // 2 x 64-col blocks

    const int hpair = blockIdx.x;    // heads 2*hpair, 2*hpair+1
    const int btp   = blockIdx.y;    // turn pair: bt = 2*btp, 2*btp+1
    const int b     = btp >> 5;
    const int tl0   = (2 * btp) & 63;
    const int row0  = btp * 256;
    const int col0  = hpair * 128;

    // ---- cp.async slots: A 1024 units (4/thread), B 512 units (2/thread) ----
    const __half* gA[4]; uint32_t dA[4];
#pragma unroll
    for (int i = 0; i < 4; i++) {
        int idx = tid + i * 256;
        int r = idx >> 2, u = idx & 3;
        gA[i] = g_tokh + (size_t)(row0 + r) * D_ + u * 8;
        dA[i] = r * 64 + ((u ^ swz(r)) << 4);
    }
    const __half* gB[2]; uint32_t dB[2];
#pragma unroll
    for (int i = 0; i < 2; i++) {
        int idx = tid + i * 256;
        int r = idx >> 2, u = idx & 3;
        gB[i] = g_Wqh + (size_t)(col0 + r) * D_ + u * 8;
        dB[i] = ABW + r * 64 + ((u ^ swz(r)) << 4);
    }

    // ---- ldmatrix lane offsets (main loop, relative to stage base) ----
    uint32_t offA[4][2], offB[4][2];
#pragma unroll
    for (int mt = 0; mt < 4; mt++)
#pragma unroll
        for (int ks = 0; ks < 2; ks++) {
            int r = warp_m * 64 + mt * 16 + (lane & 7) + ((lane >> 3) & 1) * 8;
            int u = 2 * ks + (lane >> 4);
            offA[mt][ks] = r * 64 + ((u ^ swz(r)) << 4);
        }
#pragma unroll
    for (int P = 0; P < 4; P++)
#pragma unroll
        for (int ks = 0; ks < 2; ks++) {
            int n = warp_n * 64 + P * 16 + (lane & 7) + ((lane >> 4) & 1) * 8;
            int u = 2 * ks + ((lane >> 3) & 1);
            offB[P][ks] = ABW + n * 64 + ((u ^ swz(n)) << 4);
        }

    float cacc[4][8][4];
#pragma unroll
    for (int mt = 0; mt < 4; mt++)
#pragma unroll
        for (int nt = 0; nt < 8; nt++)
#pragma unroll
            for (int i = 0; i < 4; i++) cacc[mt][nt][i] = 0.0f;

    // ---- prologue: chunks 0,1 in flight ----
#pragma unroll
    for (int c = 0; c < 2; c++) {
        const uint32_t sb = smem_s + c * STAGEB;
#pragma unroll
        for (int i = 0; i < 4; i++) cp16(sb + dA[i], gA[i] + c * 32);
#pragma unroll
        for (int i = 0; i < 2; i++) cp16(sb + dB[i], gB[i] + c * 32);
        CP_COMMIT();
    }

    // ---- main loop: 24 chunks, 3-stage pipeline ----
#pragma unroll 6
    for (int it = 0; it < 24; it++) {
        if (it == 23) cp_wait<0>(); else cp_wait<1>();
        __syncthreads();
        if (it + 2 < 24) {
            const uint32_t sb = smem_s + ((it + 2) % 3) * STAGEB;
            const int k = (it + 2) * 32;
#pragma unroll
            for (int i = 0; i < 4; i++) cp16(sb + dA[i], gA[i] + k);
#pragma unroll
            for (int i = 0; i < 2; i++) cp16(sb + dB[i], gB[i] + k);
            CP_COMMIT();
        }
        mma_stage(smem_s + (it % 3) * STAGEB, offA, offB, cacc);
    }

    // ---------------- phase 2 ----------------
    float* kbs  = reinterpret_cast<float*>(smemc + KB_OFF);   // [2][64][64]
    float* vbs  = reinterpret_cast<float*>(smemc + VB_OFF);   // [2][64][64]
    int*   sspk = reinterpret_cast<int*>(smemc + SPK_OFF);

    // stage k,v for (b, 2 heads) into disjoint scratch (before final barrier)
    {
        const float* kvb = g_kvproj + (size_t)(b * T_) * (2 * D_);
#pragma unroll
        for (int i = 0; i < 16; i++) {
            int idx = tid + i * 256;          // 0..4095 float4 slots
            int isV = idx >> 11;
            int rest = idx & 2047;
            int h = rest >> 10;
            int s2 = rest & 1023;
            int u = s2 >> 4, dq = s2 & 15;
            const float* src = kvb + (size_t)u * (2 * D_) + (size_t)isV * D_
                               + (2 * hpair + h) * HD_ + dq * 4;
            float* dst = (isV ? vbs : kbs) + h * 4096 + u * HD_ + dq * 4;
            *reinterpret_cast<float4*>(dst) = *reinterpret_cast<const float4*>(src);
        }
        if (tid < T_) sspk[tid] = spk[b * T_ + tid];
    }
    __syncthreads();   // mma(23) done; kv/spk visible

    // ---- store q (fp16) into stage regions by k-chunk ----
    // chunk kc<3: stage kc A-region; kc==3: rows 0..127 -> stage0.B, rows 128..255 -> stage1.B
    {
#pragma unroll
        for (int mt = 0; mt < 4; mt++) {
#pragma unroll
            for (int nt = 0; nt < 8; nt++) {
                int kc = warp_n * 2 + (nt >> 2);
#pragma unroll
                for (int hrow = 0; hrow < 2; hrow++) {
                    int r = warp_m * 64 + mt * 16 + gid + hrow * 8;
                    uint32_t base;
                    if (kc < 3) base = kc * STAGEB + r * 64;
                    else base = (r < 128) ? (ABW + r * 64) : (STAGEB + ABW + (r - 128) * 64);
                    uint32_t addr = base + (((nt & 3) ^ swz(r)) << 4) + c4 * 4;
                    *reinterpret_cast<uint32_t*>(smemc + addr) =
                        pack_h2(cacc[mt][nt][2 * hrow], cacc[mt][nt][2 * hrow + 1]);
                }
            }
        }
    }

    // ---- build 4 M matrices in registers (fp32, ascending u) ----
    const int mid  = tid >> 6;            // matrix 0..3
    const int tsel = mid >> 1;            // 0: t0, 1: t1
    const int h    = mid & 1;
    const int dp   = (tid & 63) >> 1;     // d pair
    const int e0   = (tid & 1) * 32;
    float m0[32], m1[32];
    {
        const int d0 = dp * 2;
        const int tl = tl0 + tsel;
        const int myspk = sspk[tl];
        const float* kb = kbs + h * 4096;
        const float* vb = vbs + h * 4096;
#pragma unroll
        for (int j = 0; j < 32; j++) { m0[j] = 0.0f; m1[j] = 0.0f; }
        for (int u = 0; u <= tl; u++) {
            if (sspk[u] != myspk) continue;
            float kd0 = kb[u * HD_ + d0];
            float kd1 = kb[u * HD_ + d0 + 1];
#pragma unroll
            for (int j4 = 0; j4 < 8; j4++) {
                float4 v4 = *reinterpret_cast<const float4*>(&vb[u * HD_ + e0 + j4 * 4]);
                m0[j4 * 4 + 0] += kd0 * v4.x; m1[j4 * 4 + 0] += kd1 * v4.x;
                m0[j4 * 4 + 1] += kd0 * v4.y; m1[j4 * 4 + 1] += kd1 * v4.y;
                m0[j4 * 4 + 2] += kd0 * v4.z; m1[j4 * 4 + 2] += kd1 * v4.z;
                m0[j4 * 4 + 3] += kd0 * v4.w; m1[j4 * 4 + 3] += kd1 * v4.w;
            }
        }
    }
    __syncthreads();   // all kbs/vbs reads done; q stores done

    // ---- zero apply-B region (64 KB at KB_OFF, overwrites kbs+vbs) ----
#pragma unroll
    for (int i = 0; i < 16; i++) {
        int idx = tid + i * 256;
        *reinterpret_cast<uint4*>(smemc + KB_OFF + idx * 16) = make_uint4(0, 0, 0, 0);
    }
    __syncthreads();

    // ---- store M^T (fp16) into apply-B: B_t[n=64h+e][k=64h+d] = M[d][e] ----
    {
        const int d0 = dp * 2;
        const int kc = 2 * h + (dp >> 4);
        const int w  = dp & 15;
        const int u  = w >> 2;
        const uint32_t tb = KB_OFF + tsel * 32768 + kc * 8192;
#pragma unroll
        for (int j = 0; j < 32; j++) {
            int n = h * 64 + e0 + j;
            uint32_t addr = tb + n * 64 + ((u ^ swz(n)) << 4) + (w & 3) * 4;
            *reinterpret_cast<uint32_t*>(smemc + addr) = pack_h2(m0[j], m1[j]);
        }
        (void)d0;
    }
    __syncthreads();

    // ---- apply: cacc = q @ blockdiag(M_t,h) over K=128 (4 chunks) ----
#pragma unroll
    for (int mt = 0; mt < 4; mt++)
#pragma unroll
        for (int nt = 0; nt < 8; nt++)
#pragma unroll
            for (int i = 0; i < 4; i++) cacc[mt][nt][i] = 0.0f;

    const int tB = warp_m >> 1;           // 0: rows t0, 1: rows t1
#pragma unroll
    for (int kc = 0; kc < 4; kc++) {
#pragma unroll
        for (int ks = 0; ks < 2; ks++) {
            uint32_t a[4][4], bb[4][4];
#pragma unroll
            for (int mt = 0; mt < 4; mt++) {
                int r = warp_m * 64 + mt * 16 + (lane & 7) + ((lane >> 3) & 1) * 8;
                int u = 2 * ks + (lane >> 4);
                uint32_t base;
                if (kc < 3) base = kc * STAGEB + r * 64;
                else base = (r < 128) ? (ABW + r * 64) : (STAGEB + ABW + (r - 128) * 64);
                ldsm4(a[mt][0], a[mt][1], a[mt][2], a[mt][3],
                      smem_s + base + ((u ^ swz(r)) << 4));
            }
#pragma unroll
            for (int P = 0; P < 4; P++) {
                int n = warp_n * 64 + P * 16 + (lane & 7) + ((lane >> 4) & 1) * 8;
                int u = 2 * ks + ((lane >> 3) & 1);
                uint32_t addr = KB_OFF + tB * 32768 + kc * 8192 + n * 64 + ((u ^ swz(n)) << 4);
                ldsm4(bb[P][0], bb[P][1], bb[P][2], bb[P][3], smem_s + addr);
            }
#pragma unroll
            for (int mt = 0; mt < 4; mt++)
#pragma unroll
                for (int nt = 0; nt < 8; nt++) {
                    const int P = nt >> 1, pp = nt & 1;
                    mma_f16(cacc[mt][nt], a[mt][0], a[mt][1], a[mt][2], a[mt][3],
                            bb[P][2 * pp], bb[P][2 * pp + 1]);
                }
        }
    }

    // ---- epilogue: out = tok + acc (exact fp32 residual) ----
#pragma unroll
    for (int mt = 0; mt < 4; mt++) {
#pragma unroll
        for (int nt = 0; nt < 8; nt++) {
            int row = row0 + warp_m * 64 + mt * 16 + gid;
            int col = col0 + warp_n * 64 + nt * 8 + c4 * 2;
            size_t a0 = (size_t)row * D_ + col;
            size_t a1 = (size_t)(row + 8) * D_ + col;
            float2 x0 = *reinterpret_cast<const float2*>(tok + a0);
            float2 x1 = *reinterpret_cast<const float2*>(tok + a1);
            *reinterpret_cast<float2*>(out + a0) =
                make_float2(cacc[mt][nt][0] + x0.x, cacc[mt][nt][1] + x0.y);
            *reinterpret_cast<float2*>(out + a1) =
                make_float2(cacc[mt][nt][2] + x1.x, cacc[mt][nt][3] + x1.y);
        }
    }
}

// -------------------- launch --------------------
extern "C" void kernel_launch(void* const* d_in, const int* in_sizes, int n_in,
                              void* d_out, int out_size) {
    const int*   spk = (const int*)d_in[1];
    const float* tok = (const float*)d_in[2];
    const float* edu = (const float*)d_in[3];
    const float* Wk  = (const float*)d_in[4];
    const float* Wv  = (const float*)d_in[5];
    const float* Wq  = (const float*)d_in[6];
    float* out = (float*)d_out;

    float* p_kvproj; cudaGetSymbolAddress((void**)&p_kvproj, g_kvproj);

    cudaFuncSetAttribute(qgemm_fused_kernel,
                         cudaFuncAttributeMaxDynamicSharedMemorySize, SMEM_BYTES);

    // 0) prep: kvproj + fp16 convert, one launch
    {
        const size_t total = (size_t)B_ * T_ * L_ * D_ + (size_t)D_ * D_;
        int conv_blocks = (int)(total / (256 * 8));   // 12576, exact
        prep_kernel<<<KV_BLOCKS + conv_blocks, 256>>>(edu, Wk, Wv, p_kvproj, tok, Wq);
    }

    // 1) fused q projection + M build + apply + residual (256x128 tile)
    {
        dim3 grid(H_ / 2, (B_ * T_) / 2);             // (6, 128)
        qgemm_fused_kernel<<<grid, 256, SMEM_BYTES>>>(tok, spk, out);
    }
}